// round 3
// baseline (speedup 1.0000x reference)
#include <cuda_runtime.h>
#include <math.h>

#define Bn 32
#define Tn 256
#define OBS 32
#define LAT 64
#define HID 400
#define P 65                      // smem pitch: 65 floats -> conflict-free rows AND cols
#define L2PI 1.8378770664093453f  // ln(2*pi)

#define XR_OFF 0
#define LL_OFF (Bn*Tn*OBS)                    // 262144
#define MQ_OFF (LL_OFF + Bn)                  // 262176
#define SQ_OFF (MQ_OFF + Bn*Tn*LAT)           // 786464

// ---------------- device scratch (no cudaMalloc allowed) ----------------
__device__ float g_Q[LAT*LAT];
__device__ float g_zmu[Bn*Tn*LAT];
__device__ float g_sig[Bn*Tn*LAT];
__device__ float g_mf [Bn*Tn*LAT];
__device__ float g_Sf [(size_t)Bn*Tn*LAT*LAT];   // 134 MB

// ---------------- 64x64 matmul helpers (require blockDim.x == 256) ------
// Thread map: tx = tid&15, ty = tid>>4. rows r0..r0+3 (r0=4*ty), cols tx+16*j.
// Row loads broadcast (2 addrs/warp); col loads hit 16 distinct consecutive
// addresses (conflict-free with pitch 65).

__device__ __forceinline__ void mm_AB_plus(float* C, const float* A, const float* Bm, const float* Add) {
    int tx = threadIdx.x & 15, ty = threadIdx.x >> 4;
    int r0 = ty * 4;
    float acc[4][4];
#pragma unroll
    for (int i = 0; i < 4; i++)
#pragma unroll
        for (int j = 0; j < 4; j++) acc[i][j] = 0.f;
#pragma unroll 4
    for (int k = 0; k < 64; k++) {
        float a0 = A[(r0+0)*P+k], a1 = A[(r0+1)*P+k], a2 = A[(r0+2)*P+k], a3 = A[(r0+3)*P+k];
        float b0 = Bm[k*P+tx], b1 = Bm[k*P+tx+16], b2 = Bm[k*P+tx+32], b3 = Bm[k*P+tx+48];
        acc[0][0] += a0*b0; acc[0][1] += a0*b1; acc[0][2] += a0*b2; acc[0][3] += a0*b3;
        acc[1][0] += a1*b0; acc[1][1] += a1*b1; acc[1][2] += a1*b2; acc[1][3] += a1*b3;
        acc[2][0] += a2*b0; acc[2][1] += a2*b1; acc[2][2] += a2*b2; acc[2][3] += a2*b3;
        acc[3][0] += a3*b0; acc[3][1] += a3*b1; acc[3][2] += a3*b2; acc[3][3] += a3*b3;
    }
#pragma unroll
    for (int i = 0; i < 4; i++)
#pragma unroll
        for (int j = 0; j < 4; j++) {
            int idx = (r0+i)*P + tx + 16*j;
            C[idx] = Add ? (acc[i][j] + Add[idx]) : acc[i][j];
        }
}

// C = Add - A@B   (M1 = Sp - K@Sp)
__device__ __forceinline__ void mm_sub(float* C, const float* A, const float* Bm, const float* Add) {
    int tx = threadIdx.x & 15, ty = threadIdx.x >> 4;
    int r0 = ty * 4;
    float acc[4][4];
#pragma unroll
    for (int i = 0; i < 4; i++)
#pragma unroll
        for (int j = 0; j < 4; j++) acc[i][j] = 0.f;
#pragma unroll 4
    for (int k = 0; k < 64; k++) {
        float a0 = A[(r0+0)*P+k], a1 = A[(r0+1)*P+k], a2 = A[(r0+2)*P+k], a3 = A[(r0+3)*P+k];
        float b0 = Bm[k*P+tx], b1 = Bm[k*P+tx+16], b2 = Bm[k*P+tx+32], b3 = Bm[k*P+tx+48];
        acc[0][0] += a0*b0; acc[0][1] += a0*b1; acc[0][2] += a0*b2; acc[0][3] += a0*b3;
        acc[1][0] += a1*b0; acc[1][1] += a1*b1; acc[1][2] += a1*b2; acc[1][3] += a1*b3;
        acc[2][0] += a2*b0; acc[2][1] += a2*b1; acc[2][2] += a2*b2; acc[2][3] += a2*b3;
        acc[3][0] += a3*b0; acc[3][1] += a3*b1; acc[3][2] += a3*b2; acc[3][3] += a3*b3;
    }
#pragma unroll
    for (int i = 0; i < 4; i++)
#pragma unroll
        for (int j = 0; j < 4; j++) {
            int idx = (r0+i)*P + tx + 16*j;
            C[idx] = Add[idx] - acc[i][j];
        }
}

// C = Add + A @ B^T
__device__ __forceinline__ void mm_ABt_plus(float* C, const float* A, const float* Bm, const float* Add) {
    int tx = threadIdx.x & 15, ty = threadIdx.x >> 4;
    int r0 = ty * 4;
    float acc[4][4];
#pragma unroll
    for (int i = 0; i < 4; i++)
#pragma unroll
        for (int j = 0; j < 4; j++) acc[i][j] = 0.f;
#pragma unroll 4
    for (int k = 0; k < 64; k++) {
        float a0 = A[(r0+0)*P+k], a1 = A[(r0+1)*P+k], a2 = A[(r0+2)*P+k], a3 = A[(r0+3)*P+k];
        float b0 = Bm[(tx   )*P+k], b1 = Bm[(tx+16)*P+k], b2 = Bm[(tx+32)*P+k], b3 = Bm[(tx+48)*P+k];
        acc[0][0] += a0*b0; acc[0][1] += a0*b1; acc[0][2] += a0*b2; acc[0][3] += a0*b3;
        acc[1][0] += a1*b0; acc[1][1] += a1*b1; acc[1][2] += a1*b2; acc[1][3] += a1*b3;
        acc[2][0] += a2*b0; acc[2][1] += a2*b1; acc[2][2] += a2*b2; acc[2][3] += a2*b3;
        acc[3][0] += a3*b0; acc[3][1] += a3*b1; acc[3][2] += a3*b2; acc[3][3] += a3*b3;
    }
#pragma unroll
    for (int i = 0; i < 4; i++)
#pragma unroll
        for (int j = 0; j < 4; j++) {
            int idx = (r0+i)*P + tx + 16*j;
            C[idx] = acc[i][j] + Add[idx];
        }
}

// C = A @ (X - Y)
__device__ __forceinline__ void mm_A_diff(float* C, const float* A, const float* X, const float* Y) {
    int tx = threadIdx.x & 15, ty = threadIdx.x >> 4;
    int r0 = ty * 4;
    float acc[4][4];
#pragma unroll
    for (int i = 0; i < 4; i++)
#pragma unroll
        for (int j = 0; j < 4; j++) acc[i][j] = 0.f;
#pragma unroll 4
    for (int k = 0; k < 64; k++) {
        float a0 = A[(r0+0)*P+k], a1 = A[(r0+1)*P+k], a2 = A[(r0+2)*P+k], a3 = A[(r0+3)*P+k];
        float b0 = X[k*P+tx   ] - Y[k*P+tx   ];
        float b1 = X[k*P+tx+16] - Y[k*P+tx+16];
        float b2 = X[k*P+tx+32] - Y[k*P+tx+32];
        float b3 = X[k*P+tx+48] - Y[k*P+tx+48];
        acc[0][0] += a0*b0; acc[0][1] += a0*b1; acc[0][2] += a0*b2; acc[0][3] += a0*b3;
        acc[1][0] += a1*b0; acc[1][1] += a1*b1; acc[1][2] += a1*b2; acc[1][3] += a1*b3;
        acc[2][0] += a2*b0; acc[2][1] += a2*b1; acc[2][2] += a2*b2; acc[2][3] += a2*b3;
        acc[3][0] += a3*b0; acc[3][1] += a3*b1; acc[3][2] += a3*b2; acc[3][3] += a3*b3;
    }
#pragma unroll
    for (int i = 0; i < 4; i++)
#pragma unroll
        for (int j = 0; j < 4; j++)
            C[(r0+i)*P + tx + 16*j] = acc[i][j];
}

// Joseph form fused: C = M1 - M1 K^T + K diag(rd) K^T
//   C[i][j] = M1[i][j] + sum_k (K[i][k]*rd[k] - M1[i][k]) * K[j][k]
__device__ __forceinline__ void jos64(float* C, const float* M1, const float* K, const float* rd) {
    int tx = threadIdx.x & 15, ty = threadIdx.x >> 4;
    int r0 = ty * 4;
    float acc[4][4];
#pragma unroll
    for (int i = 0; i < 4; i++)
#pragma unroll
        for (int j = 0; j < 4; j++) acc[i][j] = 0.f;
#pragma unroll 2
    for (int k = 0; k < 64; k++) {
        float rk = rd[k];
        float t0 = K[(r0+0)*P+k]*rk - M1[(r0+0)*P+k];
        float t1 = K[(r0+1)*P+k]*rk - M1[(r0+1)*P+k];
        float t2 = K[(r0+2)*P+k]*rk - M1[(r0+2)*P+k];
        float t3 = K[(r0+3)*P+k]*rk - M1[(r0+3)*P+k];
        float b0 = K[(tx   )*P+k], b1 = K[(tx+16)*P+k], b2 = K[(tx+32)*P+k], b3 = K[(tx+48)*P+k];
        acc[0][0] += t0*b0; acc[0][1] += t0*b1; acc[0][2] += t0*b2; acc[0][3] += t0*b3;
        acc[1][0] += t1*b0; acc[1][1] += t1*b1; acc[1][2] += t1*b2; acc[1][3] += t1*b3;
        acc[2][0] += t2*b0; acc[2][1] += t2*b1; acc[2][2] += t2*b2; acc[2][3] += t2*b3;
        acc[3][0] += t3*b0; acc[3][1] += t3*b1; acc[3][2] += t3*b2; acc[3][3] += t3*b3;
    }
#pragma unroll
    for (int i = 0; i < 4; i++)
#pragma unroll
        for (int j = 0; j < 4; j++) {
            int idx = (r0+i)*P + tx + 16*j;
            C[idx] = M1[idx] + acc[i][j];
        }
}

// ---------------- Cholesky 64x64 in shared (LDL'-scaled trick) ----------
// In-place on lower triangle of M (pitch P). Produces proper L in the lower
// triangle (incl. diag), plus dvec[i]=L[i][i] and invd[i]=1/L[i][i].
// 2 barriers per column. blockDim-agnostic. Uniform control flow required.
__device__ void chol64(float* M, float* dvec, float* invd) {
    const int tid = threadIdx.x;
    const int nt  = blockDim.x;
    for (int k = 0; k < 64; k++) {
        __syncthreads();
        if (tid == 0) {
            float d = sqrtf(M[k*P+k]);
            dvec[k] = d;
            invd[k] = 1.0f / d;
        }
        __syncthreads();
        float iv  = invd[k];
        float iv2 = iv * iv;
        for (int idx = tid; idx < 4096; idx += nt) {
            int i = idx >> 6, j = idx & 63;
            if (i > k && j > k && j <= i)
                M[i*P+j] -= M[i*P+k] * M[j*P+k] * iv2;
        }
    }
    __syncthreads();
    for (int idx = tid; idx < 4096; idx += nt) {
        int i = idx >> 6, j = idx & 63;
        if (j < i)       M[i*P+j] *= invd[j];
        else if (j == i) M[i*P+i]  = dvec[i];
    }
    __syncthreads();
}

// ---------------- column-parallel cho_solve --------------------------
// Threads 0..63: solve L Y = RHS[:,c] then L^T X = Y, write KT[c][i]=X[i][c].
// Y may alias RHS (in-place). Thread 64 (optional): forward-solve rvec into
// column 64 of Y and emit ||alpha||^2. No internal barriers.
__device__ void cho_solve64(const float* L, const float* invd, const float* RHS,
                            float* Y, float* KT, const float* rvec, float* alpha2_out) {
    int c = threadIdx.x;
    if (c < 64) {
        for (int i = 0; i < 64; i++) {
            float acc0 = RHS[i*P + c], acc1 = 0.f;
            int j = 0;
            for (; j + 1 < i; j += 2) {
                acc0 -= L[i*P+j]     * Y[j*P+c];
                acc1 += L[i*P+j+1]   * Y[(j+1)*P+c];
            }
            if (j < i) acc0 -= L[i*P+j] * Y[j*P+c];
            Y[i*P+c] = (acc0 - acc1) * invd[i];
        }
        for (int i = 63; i >= 0; i--) {
            float acc0 = Y[i*P+c], acc1 = 0.f;
            int j = i + 1;
            for (; j + 1 < 64; j += 2) {
                acc0 -= L[j*P+i]     * Y[j*P+c];
                acc1 += L[(j+1)*P+i] * Y[(j+1)*P+c];
            }
            if (j < 64) acc0 -= L[j*P+i] * Y[j*P+c];
            float xv = (acc0 - acc1) * invd[i];
            Y[i*P+c]    = xv;
            KT[c*P + i] = xv;
        }
    } else if (c == 64 && rvec != nullptr) {
        for (int i = 0; i < 64; i++) {
            float acc = rvec[i];
            for (int j = 0; j < i; j++) acc -= L[i*P+j] * Y[j*P+64];
            Y[i*P+64] = acc * invd[i];
        }
        float s = 0.f;
        for (int i = 0; i < 64; i++) { float a = Y[i*P+64]; s += a*a; }
        *alpha2_out = s;
    }
}

// ========================== kernels ====================================

__global__ void k_buildQ(const float* __restrict__ qp) {
    __shared__ float sL[LAT*P];
    int tid = threadIdx.x;
    for (int idx = tid; idx < LAT*LAT; idx += blockDim.x) {
        int i = idx >> 6, j = idx & 63;
        float v = 0.f;
        if (j <= i) { v = qp[i*(i+1)/2 + j]; if (j == i) v = expf(v); }
        sL[i*P+j] = v;
    }
    __syncthreads();
    for (int idx = tid; idx < LAT*LAT; idx += blockDim.x) {
        int i = idx >> 6, j = idx & 63;
        int m = i < j ? i : j;
        float acc = 0.f;
        for (int k = 0; k <= m; k++) acc += sL[i*P+k] * sL[j*P+k];
        g_Q[idx] = acc;
    }
}

__global__ void k_encoder(const float* __restrict__ x,
                          const float* __restrict__ W1, const float* __restrict__ b1,
                          const float* __restrict__ Wm, const float* __restrict__ bm,
                          const float* __restrict__ Wl, const float* __restrict__ bl) {
    __shared__ float xs[OBS];
    __shared__ float h[HID];
    int tok = blockIdx.x, tid = threadIdx.x;
    if (tid < OBS) xs[tid] = x[tok*OBS + tid];
    __syncthreads();
    for (int j = tid; j < HID; j += blockDim.x) {
        float acc = b1[j];
#pragma unroll
        for (int k = 0; k < OBS; k++) acc += xs[k] * W1[k*HID + j];
        h[j] = fmaxf(acc, 0.f);
    }
    __syncthreads();
    if (tid < LAT) {
        float acc = bm[tid];
        for (int j = 0; j < HID; j++) acc += h[j] * Wm[j*LAT + tid];
        g_zmu[tok*LAT + tid] = acc;
    } else if (tid < 2*LAT) {
        int o = tid - LAT;
        float acc = bl[o];
        for (int j = 0; j < HID; j++) acc += h[j] * Wl[j*LAT + o];
        g_sig[tok*LAT + o] = expf(0.5f * acc);
    }
}

__global__ void __launch_bounds__(256, 1)
k_filter(const float* __restrict__ Amat, const float* __restrict__ bvec_g,
         const int* __restrict__ mask, float* __restrict__ out_ll) {
    extern __shared__ float sm[];
    float* sA   = sm;
    float* sAT  = sA   + LAT*P;
    float* sQ   = sAT  + LAT*P;
    float* sSig = sQ   + LAT*P;
    float* sT1  = sSig + LAT*P;
    float* sSp  = sT1  + LAT*P;
    float* sS   = sSp  + LAT*P;
    float* sK   = sS   + LAT*P;
    float* vb   = sK   + LAT*P;
    float* mu   = vb;        float* mup  = mu   + 64;
    float* muu  = mup + 64;  float* r    = muu  + 64;
    float* rd   = r   + 64;  float* bv   = rd   + 64;
    float* dvec = bv  + 64;  float* invd = dvec + 64;
    float* scal = invd + 64;  // [0]=alpha2 [1]=sumlog [2]=ll

    int b = blockIdx.x, tid = threadIdx.x;

    for (int idx = tid; idx < LAT*LAT; idx += 256) {
        int i = idx >> 6, j = idx & 63;
        float a = Amat[idx];
        sA [i*P+j] = a;
        sAT[j*P+i] = a;
        sQ [i*P+j] = g_Q[idx];
        sSig[i*P+j] = (i == j) ? 1.f : 0.f;
    }
    if (tid < 64) { mu[tid] = 0.f; bv[tid] = bvec_g[tid]; }
    if (tid == 0) scal[2] = 0.f;
    __syncthreads();

    for (int t = 0; t < Tn; t++) {
        int base = (b*Tn + t) * LAT;
        int m = mask[b*Tn + t];

        if (tid < 64) {
            float acc = bv[tid];
            for (int k = 0; k < 64; k++) acc += sA[tid*P+k] * mu[k];
            mup[tid] = acc;
            r[tid]   = g_zmu[base + tid] - acc;
            rd[tid]  = g_sig[base + tid];
        }
        __syncthreads();

        mm_AB_plus(sT1, sA, sSig, nullptr);          // T1 = A @ Sig
        __syncthreads();
        mm_AB_plus(sSp, sT1, sAT, sQ);               // Sp = T1 @ A^T + Q
        __syncthreads();

        if (m) {
            if (tid < 64) mu[tid] = mup[tid];
            for (int idx = tid; idx < LAT*LAT; idx += 256) {
                int i = idx >> 6, j = idx & 63;
                sSig[i*P+j] = sSp[i*P+j];
            }
        } else {
            for (int idx = tid; idx < LAT*LAT; idx += 256) {
                int i = idx >> 6, j = idx & 63;
                sS[i*P+j] = sSp[i*P+j] + ((i == j) ? rd[i] : 0.f);
            }
            chol64(sS, dvec, invd);                  // L in sS
            cho_solve64(sS, invd, sSp, sT1, sK, r, &scal[0]);  // K = (S^-1 Sp)^T
            if (tid == 65) {
                float s = 0.f;
                for (int i = 0; i < 64; i++) s += logf(dvec[i]);
                scal[1] = s;
            }
            __syncthreads();

            if (tid < 64) {
                float acc = mup[tid];
                for (int k = 0; k < 64; k++) acc += sK[tid*P+k] * r[k];
                muu[tid] = acc;
            }
            mm_sub(sT1, sK, sSp, sSp);               // M1 = Sp - K@Sp = (I-K)Sp
            __syncthreads();
            jos64(sSig, sT1, sK, rd);                // Sig = M1(I-K)^T + K R K^T
            if (tid < 64) mu[tid] = muu[tid];
            if (tid == 0)
                scal[2] += -0.5f * 64.f * L2PI - scal[1] - 0.5f * scal[0];
        }
        __syncthreads();

        if (tid < 64) g_mf[base + tid] = mu[tid];
        for (int idx = tid; idx < LAT*LAT; idx += 256)
            g_Sf[(size_t)base * 64 + idx] = sSig[(idx >> 6)*P + (idx & 63)];
        __syncthreads();
    }
    if (tid == 0) out_ll[b] = scal[2];
}

__global__ void __launch_bounds__(256, 1)
k_smoother(const float* __restrict__ Amat, const float* __restrict__ bvec_g,
           float* __restrict__ out) {
    extern __shared__ float sm[];
    float* sA   = sm;
    float* sAT  = sA   + LAT*P;
    float* sQ   = sAT  + LAT*P;
    float* sSf  = sQ   + LAT*P;
    float* sSs  = sSf  + LAT*P;
    float* sT1  = sSs  + LAT*P;
    float* sSp  = sT1  + LAT*P;
    float* sS   = sSp  + LAT*P;
    float* sG   = sS   + LAT*P;
    float* vb   = sG   + LAT*P;
    float* mfv    = vb;          float* mus  = mfv    + 64;
    float* mupred = mus  + 64;   float* dm   = mupred + 64;
    float* nmu    = dm   + 64;   float* bv   = nmu    + 64;
    float* dvec   = bv   + 64;   float* invd = dvec   + 64;

    int b = blockIdx.x, tid = threadIdx.x;
    float* out_mq = out + MQ_OFF;
    float* out_sq = out + SQ_OFF;

    for (int idx = tid; idx < LAT*LAT; idx += 256) {
        int i = idx >> 6, j = idx & 63;
        float a = Amat[idx];
        sA [i*P+j] = a;
        sAT[j*P+i] = a;
        sQ [i*P+j] = g_Q[idx];
    }
    size_t baseT = ((size_t)b*Tn + (Tn-1)) * LAT;
    if (tid < 64) {
        mus[tid] = g_mf[baseT + tid];
        bv[tid]  = bvec_g[tid];
        out_mq[baseT + tid] = mus[tid];
    }
    for (int idx = tid; idx < LAT*LAT; idx += 256) {
        float v = g_Sf[baseT*64 + idx];
        sSs[(idx >> 6)*P + (idx & 63)] = v;
        out_sq[baseT*64 + idx] = v;
    }
    __syncthreads();

    for (int t = Tn - 2; t >= 0; t--) {
        size_t base = ((size_t)b*Tn + t) * LAT;
        if (tid < 64) mfv[tid] = g_mf[base + tid];
        for (int idx = tid; idx < LAT*LAT; idx += 256)
            sSf[(idx >> 6)*P + (idx & 63)] = g_Sf[base*64 + idx];
        __syncthreads();

        if (tid < 64) {
            float acc = bv[tid];
            for (int k = 0; k < 64; k++) acc += sA[tid*P+k] * mfv[k];
            mupred[tid] = acc;
            dm[tid] = mus[tid] - acc;
        }
        __syncthreads();

        mm_AB_plus(sT1, sA, sSf, nullptr);           // T1 = A @ Sf
        __syncthreads();
        mm_AB_plus(sSp, sT1, sAT, sQ);               // Spred = T1 @ A^T + Q
        __syncthreads();
        for (int idx = tid; idx < LAT*LAT; idx += 256) {
            int i = idx >> 6, j = idx & 63;
            sS[i*P+j] = sSp[i*P+j];
        }
        chol64(sS, dvec, invd);
        cho_solve64(sS, invd, sT1, sT1, sG, nullptr, nullptr);  // G = (Spred^-1 T1)^T
        __syncthreads();

        if (tid < 64) {
            float acc = mfv[tid];
            for (int k = 0; k < 64; k++) acc += sG[tid*P+k] * dm[k];
            nmu[tid] = acc;
        }
        mm_A_diff(sT1, sG, sSs, sSp);                // M1 = G @ (Ss - Spred)
        __syncthreads();
        mm_ABt_plus(sSs, sT1, sG, sSf);              // Ss = Sf + M1 @ G^T
        if (tid < 64) mus[tid] = nmu[tid];
        __syncthreads();

        if (tid < 64) out_mq[base + tid] = mus[tid];
        for (int idx = tid; idx < LAT*LAT; idx += 256)
            out_sq[base*64 + idx] = sSs[(idx >> 6)*P + (idx & 63)];
        __syncthreads();
    }
}

__global__ void k_sample(const float* __restrict__ eps,
                         const float* __restrict__ Wd, const float* __restrict__ bd,
                         float* __restrict__ out) {
    __shared__ float sM[LAT*P];
    __shared__ float ev[64], zv[64], dvec[64], invd[64];
    int tok = blockIdx.x, tid = threadIdx.x;
    const float* sq = out + SQ_OFF + (size_t)tok * (LAT*LAT);
    const float* mq = out + MQ_OFF + tok * LAT;

    for (int idx = tid; idx < LAT*LAT; idx += blockDim.x) {
        int i = idx >> 6, j = idx & 63;
        sM[i*P+j] = sq[idx] + ((i == j) ? 1e-5f : 0.f);
    }
    if (tid < 64) ev[tid] = eps[tok*LAT + tid];
    chol64(sM, dvec, invd);   // internal leading barrier covers the loads

    if (tid < 64) {
        float acc = mq[tid];
        for (int j = 0; j <= tid; j++) acc += sM[tid*P+j] * ev[j];  // diag == dvec
        zv[tid] = acc;
    }
    __syncthreads();
    if (tid < OBS) {
        float acc = bd[tid];
        for (int i = 0; i < 64; i++) acc += zv[i] * Wd[i*OBS + tid];
        out[XR_OFF + tok*OBS + tid] = acc;
    }
}

// ========================== launch ====================================

extern "C" void kernel_launch(void* const* d_in, const int* in_sizes, int n_in,
                              void* d_out, int out_size) {
    const float* x    = (const float*)d_in[0];
    const int*   mask = (const int*)  d_in[1];
    const float* eps  = (const float*)d_in[2];
    const float* W1   = (const float*)d_in[3];
    const float* b1   = (const float*)d_in[4];
    const float* Wm   = (const float*)d_in[5];
    const float* bm   = (const float*)d_in[6];
    const float* Wl   = (const float*)d_in[7];
    const float* bl   = (const float*)d_in[8];
    const float* Wd   = (const float*)d_in[9];
    const float* bd   = (const float*)d_in[10];
    const float* A    = (const float*)d_in[11];
    const float* bvec = (const float*)d_in[12];
    const float* Qp   = (const float*)d_in[13];
    float* out = (float*)d_out;

    k_buildQ <<<1, 256>>>(Qp);
    k_encoder<<<Bn*Tn, 128>>>(x, W1, b1, Wm, bm, Wl, bl);

    size_t smemF = (size_t)(8*LAT*P + 9*64 + 16) * sizeof(float);   // ~135.5 KB
    cudaFuncSetAttribute(k_filter, cudaFuncAttributeMaxDynamicSharedMemorySize, (int)smemF);
    k_filter<<<Bn, 256, smemF>>>(A, bvec, mask, out + LL_OFF);

    size_t smemS = (size_t)(9*LAT*P + 8*64 + 16) * sizeof(float);   // ~152 KB
    cudaFuncSetAttribute(k_smoother, cudaFuncAttributeMaxDynamicSharedMemorySize, (int)smemS);
    k_smoother<<<Bn, 256, smemS>>>(A, bvec, out);

    k_sample<<<Bn*Tn, 128>>>(eps, Wd, bd, out);
}

// round 5
// speedup vs baseline: 1.8471x; 1.8471x over previous
#include <cuda_runtime.h>
#include <math.h>

#define Bn 32
#define Tn 256
#define OBS 32
#define LAT 64
#define HID 400
#define P 68                      // pitch: %4==0 for float4
#define L2PI 1.8378770664093453f

#define XR_OFF 0
#define LL_OFF (Bn*Tn*OBS)
#define MQ_OFF (LL_OFF + Bn)
#define SQ_OFF (MQ_OFF + Bn*Tn*LAT)

__device__ float g_Q[LAT*LAT];
__device__ float g_zmu[Bn*Tn*LAT];
__device__ float g_sig[Bn*Tn*LAT];
__device__ float g_mf [Bn*Tn*LAT];
__device__ __align__(16) float g_Sf [(size_t)Bn*Tn*LAT*LAT];

// ---------------- f32x2 helpers ----------------
__device__ __forceinline__ unsigned long long pk2(float lo, float hi) {
    unsigned long long r;
    asm("mov.b64 %0, {%1,%2};" : "=l"(r) : "f"(lo), "f"(hi));
    return r;
}
__device__ __forceinline__ void upk2(unsigned long long v, float& lo, float& hi) {
    asm("mov.b64 {%0,%1}, %2;" : "=f"(lo), "=f"(hi) : "l"(v));
}
__device__ __forceinline__ void ffma2(unsigned long long& c, unsigned long long a, unsigned long long b) {
    asm("fma.rn.f32x2 %0, %1, %2, %0;" : "+l"(c) : "l"(a), "l"(b));
}

// ---------------- 64x64 matmul, 256 threads, 4x4 tiles, f32x2 ----------
// tx=tid&15 -> cols 4tx..4tx+3 ; ty=tid>>4 -> rows 4ty..4ty+3
// ATMODE: C = A^T@B; else C = A@B. BDIFF: B := (B - B2).
// EPI: 0 C=acc, 1 C=Add+acc, 2 C=Add-acc.
#define MM_MICRO(A0,A1,A2,A3,BV) do{                                     \
    unsigned long long bp0 = pk2((BV).x,(BV).y), bp1 = pk2((BV).z,(BV).w);\
    unsigned long long d_;                                               \
    d_ = pk2(A0,A0); ffma2(acc[0][0],d_,bp0); ffma2(acc[0][1],d_,bp1);   \
    d_ = pk2(A1,A1); ffma2(acc[1][0],d_,bp0); ffma2(acc[1][1],d_,bp1);   \
    d_ = pk2(A2,A2); ffma2(acc[2][0],d_,bp0); ffma2(acc[2][1],d_,bp1);   \
    d_ = pk2(A3,A3); ffma2(acc[3][0],d_,bp0); ffma2(acc[3][1],d_,bp1);   \
}while(0)

template<int EPI, bool ATMODE, bool BDIFF>
__device__ __forceinline__ void mm64(float* C, const float* A, const float* B,
                                     const float* B2, const float* Add) {
    int tx = threadIdx.x & 15, ty = threadIdx.x >> 4;
    int i0 = 4*ty, j0 = 4*tx;
    unsigned long long acc[4][2];
#pragma unroll
    for (int i = 0; i < 4; i++) { acc[i][0] = 0ull; acc[i][1] = 0ull; }
#pragma unroll 2
    for (int kk = 0; kk < 64; kk += 4) {
        float4 b0 = *(const float4*)&B[(kk+0)*P + j0];
        float4 b1 = *(const float4*)&B[(kk+1)*P + j0];
        float4 b2 = *(const float4*)&B[(kk+2)*P + j0];
        float4 b3 = *(const float4*)&B[(kk+3)*P + j0];
        if (BDIFF) {
            float4 c0 = *(const float4*)&B2[(kk+0)*P + j0];
            float4 c1 = *(const float4*)&B2[(kk+1)*P + j0];
            float4 c2 = *(const float4*)&B2[(kk+2)*P + j0];
            float4 c3 = *(const float4*)&B2[(kk+3)*P + j0];
            b0.x-=c0.x; b0.y-=c0.y; b0.z-=c0.z; b0.w-=c0.w;
            b1.x-=c1.x; b1.y-=c1.y; b1.z-=c1.z; b1.w-=c1.w;
            b2.x-=c2.x; b2.y-=c2.y; b2.z-=c2.z; b2.w-=c2.w;
            b3.x-=c3.x; b3.y-=c3.y; b3.z-=c3.z; b3.w-=c3.w;
        }
        if (!ATMODE) {
            float4 a0 = *(const float4*)&A[(i0+0)*P + kk];
            float4 a1 = *(const float4*)&A[(i0+1)*P + kk];
            float4 a2 = *(const float4*)&A[(i0+2)*P + kk];
            float4 a3 = *(const float4*)&A[(i0+3)*P + kk];
            MM_MICRO(a0.x,a1.x,a2.x,a3.x, b0);
            MM_MICRO(a0.y,a1.y,a2.y,a3.y, b1);
            MM_MICRO(a0.z,a1.z,a2.z,a3.z, b2);
            MM_MICRO(a0.w,a1.w,a2.w,a3.w, b3);
        } else {
            float4 a0 = *(const float4*)&A[(kk+0)*P + i0];
            float4 a1 = *(const float4*)&A[(kk+1)*P + i0];
            float4 a2 = *(const float4*)&A[(kk+2)*P + i0];
            float4 a3 = *(const float4*)&A[(kk+3)*P + i0];
            MM_MICRO(a0.x,a0.y,a0.z,a0.w, b0);
            MM_MICRO(a1.x,a1.y,a1.z,a1.w, b1);
            MM_MICRO(a2.x,a2.y,a2.z,a2.w, b2);
            MM_MICRO(a3.x,a3.y,a3.z,a3.w, b3);
        }
    }
#pragma unroll
    for (int i = 0; i < 4; i++) {
        float v0,v1,v2,v3;
        upk2(acc[i][0], v0, v1);
        upk2(acc[i][1], v2, v3);
        float4 r;
        if (EPI == 0) r = make_float4(v0,v1,v2,v3);
        else {
            float4 ad = *(const float4*)&Add[(i0+i)*P + j0];
            if (EPI == 1) r = make_float4(ad.x+v0, ad.y+v1, ad.z+v2, ad.w+v3);
            else          r = make_float4(ad.x-v0, ad.y-v1, ad.z-v2, ad.w-v3);
        }
        *(float4*)&C[(i0+i)*P + j0] = r;
    }
}

// ---- fused Joseph: C = M1 + (K*diag(rd) - M1) @ K^T  (all row-major) ----
__device__ __forceinline__ void jos64f(float* C, const float* M1, const float* K,
                                       const float* rd) {
    int tx = threadIdx.x & 15, ty = threadIdx.x >> 4;
    int i0 = 4*ty, j0 = 4*tx;
    unsigned long long acc[4][4];
#pragma unroll
    for (int i = 0; i < 4; i++)
#pragma unroll
        for (int j = 0; j < 4; j++) acc[i][j] = 0ull;
    for (int kk = 0; kk < 64; kk += 4) {
        float4 rv = *(const float4*)&rd[kk];
        float4 lj[4];
#pragma unroll
        for (int c = 0; c < 4; c++) lj[c] = *(const float4*)&K[(j0+c)*P + kk];
        unsigned long long ljp[4][2];
#pragma unroll
        for (int c = 0; c < 4; c++) {
            ljp[c][0] = pk2(lj[c].x, lj[c].y);
            ljp[c][1] = pk2(lj[c].z, lj[c].w);
        }
#pragma unroll
        for (int i = 0; i < 4; i++) {
            float4 tk = *(const float4*)&K [(i0+i)*P + kk];
            float4 tm = *(const float4*)&M1[(i0+i)*P + kk];
            float4 t;
            t.x = tk.x*rv.x - tm.x;
            t.y = tk.y*rv.y - tm.y;
            t.z = tk.z*rv.z - tm.z;
            t.w = tk.w*rv.w - tm.w;
            unsigned long long t01 = pk2(t.x, t.y), t23 = pk2(t.z, t.w);
#pragma unroll
            for (int c = 0; c < 4; c++) {
                ffma2(acc[i][c], t01, ljp[c][0]);
                ffma2(acc[i][c], t23, ljp[c][1]);
            }
        }
    }
#pragma unroll
    for (int i = 0; i < 4; i++) {
        float4 m = *(const float4*)&M1[(i0+i)*P + j0];
        float lo, hi, v[4];
#pragma unroll
        for (int c = 0; c < 4; c++) { upk2(acc[i][c], lo, hi); v[c] = lo + hi; }
        float4 r = make_float4(m.x+v[0], m.y+v[1], m.z+v[2], m.w+v[3]);
        *(float4*)&C[(i0+i)*P + j0] = r;
    }
}

// ---------------- blocked Cholesky 64x64, panel=8, 256 threads ----------
__device__ void chol64b(float* M, float* dvec, float* invd) {
    const int tid = threadIdx.x;
    const int tx = tid & 15, ty = tid >> 4;
    const int i0 = 4*ty, j0 = 4*tx;
    for (int p = 0; p < 64; p += 8) {
        for (int k = p; k < p + 8; k++) {
            __syncthreads();
            float iv2 = 1.0f / M[k*P+k];
            int idx = tid;
#pragma unroll
            for (int rr = 0; rr < 2; rr++, idx += 256) {
                int i = idx >> 3, j = p + (idx & 7);
                if (i > k && j > k && j <= i)
                    M[i*P+j] -= M[i*P+k] * M[j*P+k] * iv2;
            }
        }
        __syncthreads();
        if (tid < 8) {
            int i = p + tid;
            float d = sqrtf(M[i*P+i]);
            dvec[i] = d;
            invd[i] = 1.0f / d;
        }
        __syncthreads();
        {
            int idx = tid;
#pragma unroll
            for (int rr = 0; rr < 2; rr++, idx += 256) {
                int i = idx >> 3, j = p + (idx & 7);
                if (j < i)       M[i*P+j] *= invd[j];
                else if (j == i) M[i*P+i]  = dvec[i];
            }
        }
        __syncthreads();
        if (p + 8 < 64 && i0 >= p + 8 && j0 >= p + 8) {
            float4 lj[4][2];
#pragma unroll
            for (int c = 0; c < 4; c++) {
                lj[c][0] = *(const float4*)&M[(j0+c)*P + p];
                lj[c][1] = *(const float4*)&M[(j0+c)*P + p + 4];
            }
#pragma unroll
            for (int r = 0; r < 4; r++) {
                float4 li0 = *(const float4*)&M[(i0+r)*P + p];
                float4 li1 = *(const float4*)&M[(i0+r)*P + p + 4];
                float4 mr  = *(const float4*)&M[(i0+r)*P + j0];
                float s0 = li0.x*lj[0][0].x + li0.y*lj[0][0].y + li0.z*lj[0][0].z + li0.w*lj[0][0].w
                         + li1.x*lj[0][1].x + li1.y*lj[0][1].y + li1.z*lj[0][1].z + li1.w*lj[0][1].w;
                float s1 = li0.x*lj[1][0].x + li0.y*lj[1][0].y + li0.z*lj[1][0].z + li0.w*lj[1][0].w
                         + li1.x*lj[1][1].x + li1.y*lj[1][1].y + li1.z*lj[1][1].z + li1.w*lj[1][1].w;
                float s2 = li0.x*lj[2][0].x + li0.y*lj[2][0].y + li0.z*lj[2][0].z + li0.w*lj[2][0].w
                         + li1.x*lj[2][1].x + li1.y*lj[2][1].y + li1.z*lj[2][1].z + li1.w*lj[2][1].w;
                float s3 = li0.x*lj[3][0].x + li0.y*lj[3][0].y + li0.z*lj[3][0].z + li0.w*lj[3][0].w
                         + li1.x*lj[3][1].x + li1.y*lj[3][1].y + li1.z*lj[3][1].z + li1.w*lj[3][1].w;
                mr.x -= s0; mr.y -= s1; mr.z -= s2; mr.w -= s3;
                *(float4*)&M[(i0+r)*P + j0] = mr;
            }
        }
    }
    __syncthreads();
}

// ---- cho_solve (R1-proven): K = (S^-1 RHS)^T; t64: alpha, ||a||^2; t65 logdet ----
__device__ void cho_solve64(const float* L, const float* invd, const float* dvec,
                            const float* RHS, float* Y, float* KT,
                            const float* rvec, float* alpha, float* scal) {
    int c = threadIdx.x;
    if (c < 64) {
        for (int i = 0; i < 64; i++) {
            float a0 = RHS[i*P+c], a1 = 0.f, a2 = 0.f, a3 = 0.f;
            int j = 0;
            for (; j + 3 < i; j += 4) {
                a0 -= L[i*P+j  ] * Y[(j  )*P+c];
                a1 += L[i*P+j+1] * Y[(j+1)*P+c];
                a2 -= L[i*P+j+2] * Y[(j+2)*P+c];
                a3 += L[i*P+j+3] * Y[(j+3)*P+c];
            }
            for (; j < i; j++) a0 -= L[i*P+j] * Y[j*P+c];
            Y[i*P+c] = (a0 - a1 + a2 - a3) * invd[i];
        }
        for (int i = 63; i >= 0; i--) {
            float a0 = Y[i*P+c], a1 = 0.f, a2 = 0.f, a3 = 0.f;
            int j = i + 1;
            for (; j + 3 < 64; j += 4) {
                a0 -= L[(j  )*P+i] * Y[(j  )*P+c];
                a1 += L[(j+1)*P+i] * Y[(j+1)*P+c];
                a2 -= L[(j+2)*P+i] * Y[(j+2)*P+c];
                a3 += L[(j+3)*P+i] * Y[(j+3)*P+c];
            }
            for (; j < 64; j++) a0 -= L[j*P+i] * Y[j*P+c];
            float xv = (a0 - a1 + a2 - a3) * invd[i];
            Y[i*P+c]    = xv;
            KT[c*P + i] = xv;
        }
    } else if (c == 64) {
        for (int i = 0; i < 64; i++) {
            float acc = rvec[i];
            for (int j = 0; j < i; j++) acc -= L[i*P+j] * alpha[j];
            alpha[i] = acc * invd[i];
        }
        float s = 0.f;
        for (int i = 0; i < 64; i++) { float a = alpha[i]; s += a*a; }
        scal[0] = s;
    } else if (c == 65) {
        float s = 0.f;
        for (int i = 0; i < 64; i++) s += logf(dvec[i]);
        scal[1] = s;
    }
}

// -------- full cho_solve in place (smoother): Y[:,c] <- L^-T L^-1 Y[:,c] ----
__device__ void cho_solve_full(const float* L, const float* invd, float* Y) {
    int c = threadIdx.x;
    if (c >= 64) return;
    for (int i = 0; i < 64; i++) {
        float a0 = Y[i*P+c], a1 = 0.f, a2 = 0.f, a3 = 0.f;
        int j = 0;
        for (; j + 3 < i; j += 4) {
            a0 -= L[i*P+j  ] * Y[(j  )*P+c];
            a1 += L[i*P+j+1] * Y[(j+1)*P+c];
            a2 -= L[i*P+j+2] * Y[(j+2)*P+c];
            a3 += L[i*P+j+3] * Y[(j+3)*P+c];
        }
        for (; j < i; j++) a0 -= L[i*P+j] * Y[j*P+c];
        Y[i*P+c] = (a0 - a1 + a2 - a3) * invd[i];
    }
    for (int i = 63; i >= 0; i--) {
        float a0 = Y[i*P+c], a1 = 0.f, a2 = 0.f, a3 = 0.f;
        int j = i + 1;
        for (; j + 3 < 64; j += 4) {
            a0 -= L[(j  )*P+i] * Y[(j  )*P+c];
            a1 += L[(j+1)*P+i] * Y[(j+1)*P+c];
            a2 -= L[(j+2)*P+i] * Y[(j+2)*P+c];
            a3 += L[(j+3)*P+i] * Y[(j+3)*P+c];
        }
        for (; j < 64; j++) a0 -= L[j*P+i] * Y[j*P+c];
        Y[i*P+c] = (a0 - a1 + a2 - a3) * invd[i];
    }
}

// ========================== kernels ====================================

__global__ void k_buildQ(const float* __restrict__ qp) {
    __shared__ float sL[LAT*P];
    int tid = threadIdx.x;
    for (int idx = tid; idx < LAT*LAT; idx += blockDim.x) {
        int i = idx >> 6, j = idx & 63;
        float v = 0.f;
        if (j <= i) { v = qp[i*(i+1)/2 + j]; if (j == i) v = expf(v); }
        sL[i*P+j] = v;
    }
    __syncthreads();
    for (int idx = tid; idx < LAT*LAT; idx += blockDim.x) {
        int i = idx >> 6, j = idx & 63;
        int m = i < j ? i : j;
        float acc = 0.f;
        for (int k = 0; k <= m; k++) acc += sL[i*P+k] * sL[j*P+k];
        g_Q[idx] = acc;
    }
}

__global__ void k_encoder(const float* __restrict__ x,
                          const float* __restrict__ W1, const float* __restrict__ b1,
                          const float* __restrict__ Wm, const float* __restrict__ bm,
                          const float* __restrict__ Wl, const float* __restrict__ bl) {
    __shared__ float xs[OBS];
    __shared__ float h[HID];
    int tok = blockIdx.x, tid = threadIdx.x;
    if (tid < OBS) xs[tid] = x[tok*OBS + tid];
    __syncthreads();
    for (int j = tid; j < HID; j += blockDim.x) {
        float acc = b1[j];
#pragma unroll
        for (int k = 0; k < OBS; k++) acc += xs[k] * W1[k*HID + j];
        h[j] = fmaxf(acc, 0.f);
    }
    __syncthreads();
    if (tid < LAT) {
        float acc = bm[tid];
        for (int j = 0; j < HID; j++) acc += h[j] * Wm[j*LAT + tid];
        g_zmu[tok*LAT + tid] = acc;
    } else if (tid < 2*LAT) {
        int o = tid - LAT;
        float acc = bl[o];
        for (int j = 0; j < HID; j++) acc += h[j] * Wl[j*LAT + o];
        g_sig[tok*LAT + o] = expf(0.5f * acc);
    }
}

__global__ void __launch_bounds__(256, 1)
k_filter(const float* __restrict__ Amat, const float* __restrict__ bvec_g,
         const int* __restrict__ mask, float* __restrict__ out_ll) {
    extern __shared__ float sm[];
    float* sA   = sm;
    float* sAT  = sA   + LAT*P;
    float* sQ   = sAT  + LAT*P;
    float* sSig = sQ   + LAT*P;
    float* sT1  = sSig + LAT*P;
    float* sSp  = sT1  + LAT*P;
    float* sS   = sSp  + LAT*P;
    float* sK   = sS   + LAT*P;
    float* vb   = sK   + LAT*P;
    float* mu    = vb;          float* mup  = mu    + 64;
    float* r     = mup  + 64;   float* rd   = r     + 64;
    float* bv    = rd   + 64;   float* dvec = bv    + 64;
    float* invd  = dvec + 64;   float* alpha= invd  + 64;
    float* scal  = alpha + 64;

    int b = blockIdx.x, tid = threadIdx.x;

    for (int idx = tid; idx < LAT*LAT; idx += 256) {
        int i = idx >> 6, j = idx & 63;
        float a = Amat[idx];
        sA [i*P+j] = a;
        sAT[j*P+i] = a;
        sQ [i*P+j] = g_Q[idx];
        sSig[i*P+j] = (i == j) ? 1.f : 0.f;
    }
    if (tid < 64) { mu[tid] = 0.f; bv[tid] = bvec_g[tid]; }
    if (tid == 0) scal[2] = 0.f;
    __syncthreads();

    for (int t = 0; t < Tn; t++) {
        int base = (b*Tn + t) * LAT;
        int m = mask[b*Tn + t];

        if (tid < 64) {
            float acc = bv[tid];
            for (int k = 0; k < 64; k++) acc += sAT[k*P+tid] * mu[k];
            mup[tid] = acc;
            r[tid]   = g_zmu[base + tid] - acc;
            rd[tid]  = g_sig[base + tid];
        }
        __syncthreads();

        mm64<0,false,false>(sT1, sA, sSig, nullptr, nullptr);   // T1 = A Sig
        __syncthreads();
        mm64<1,false,false>(sSp, sT1, sAT, nullptr, sQ);        // Sp = T1 A^T + Q
        __syncthreads();

        if (m) {
            if (tid < 64) mu[tid] = mup[tid];
            for (int idx = tid; idx < 1024; idx += 256) {
                int row = idx >> 4, c4 = (idx & 15) * 4;
                *(float4*)&sSig[row*P + c4] = *(const float4*)&sSp[row*P + c4];
            }
        } else {
            for (int idx = tid; idx < 4096; idx += 256) {
                int i = idx >> 6, j = idx & 63;
                float v = sSp[i*P+j];
                if (i == j) v += rd[i];
                sS[i*P+j] = v;
            }
            chol64b(sS, dvec, invd);                            // L in sS
            cho_solve64(sS, invd, dvec, sSp, sT1, sK, r, alpha, scal);  // K = (S^-1 Sp)^T
            __syncthreads();

            if (tid < 64) {
                float acc = mup[tid];
                for (int k = 0; k < 64; k++) acc += sK[tid*P+k] * r[k];
                mu[tid] = acc;
            }
            if (tid == 64)
                scal[2] += -0.5f * 64.f * L2PI - scal[1] - 0.5f * scal[0];
            mm64<2,false,false>(sT1, sK, sSp, nullptr, sSp);    // M1 = Sp - K Sp
            __syncthreads();
            jos64f(sSig, sT1, sK, rd);                          // Joseph form
        }
        __syncthreads();

        if (tid < 64) g_mf[base + tid] = mu[tid];
        for (int idx = tid; idx < 1024; idx += 256) {
            int row = idx >> 4, c4 = (idx & 15) * 4;
            *(float4*)&g_Sf[(size_t)base*64 + row*64 + c4] =
                *(const float4*)&sSig[row*P + c4];
        }
        __syncthreads();
    }
    if (tid == 0) out_ll[b] = scal[2];
}

__global__ void __launch_bounds__(256, 1)
k_smoother(const float* __restrict__ Amat, const float* __restrict__ bvec_g,
           float* __restrict__ out) {
    extern __shared__ float sm[];
    float* sA   = sm;
    float* sAT  = sA   + LAT*P;
    float* sQ   = sAT  + LAT*P;
    float* sSf  = sQ   + LAT*P;
    float* sSs  = sSf  + LAT*P;
    float* sY   = sSs  + LAT*P;
    float* sSp  = sY   + LAT*P;
    float* sS   = sSp  + LAT*P;
    float* sD   = sS   + LAT*P;
    float* vb   = sD   + LAT*P;
    float* mfv    = vb;          float* mus  = mfv    + 64;
    float* dm     = mus  + 64;   float* bv   = dm     + 64;
    float* dvec   = bv   + 64;   float* invd = dvec   + 64;

    int b = blockIdx.x, tid = threadIdx.x;
    float* out_mq = out + MQ_OFF;
    float* out_sq = out + SQ_OFF;

    for (int idx = tid; idx < LAT*LAT; idx += 256) {
        int i = idx >> 6, j = idx & 63;
        float a = Amat[idx];
        sA [i*P+j] = a;
        sAT[j*P+i] = a;
        sQ [i*P+j] = g_Q[idx];
    }
    size_t baseT = ((size_t)b*Tn + (Tn-1)) * LAT;
    if (tid < 64) {
        mus[tid] = g_mf[baseT + tid];
        bv[tid]  = bvec_g[tid];
        out_mq[baseT + tid] = mus[tid];
    }
    for (int idx = tid; idx < 1024; idx += 256) {
        int row = idx >> 4, c4 = (idx & 15) * 4;
        float4 v = *(const float4*)&g_Sf[baseT*64 + row*64 + c4];
        *(float4*)&sSs[row*P + c4] = v;
        *(float4*)&out_sq[baseT*64 + row*64 + c4] = v;
    }
    __syncthreads();

    for (int t = Tn - 2; t >= 0; t--) {
        size_t base = ((size_t)b*Tn + t) * LAT;
        if (tid < 64) mfv[tid] = g_mf[base + tid];
        for (int idx = tid; idx < 1024; idx += 256) {
            int row = idx >> 4, c4 = (idx & 15) * 4;
            *(float4*)&sSf[row*P + c4] = *(const float4*)&g_Sf[base*64 + row*64 + c4];
        }
        __syncthreads();

        if (tid < 64) {
            float acc = bv[tid];
            for (int k = 0; k < 64; k++) acc += sAT[k*P+tid] * mfv[k];
            dm[tid] = mus[tid] - acc;
        }
        __syncthreads();

        mm64<0,false,false>(sY, sA, sSf, nullptr, nullptr);     // Y0 = A Sf
        __syncthreads();
        mm64<1,false,false>(sSp, sY, sAT, nullptr, sQ);         // Sp = Y0 A^T + Q
        __syncthreads();
        for (int idx = tid; idx < 1024; idx += 256) {
            int row = idx >> 4, c4 = (idx & 15) * 4;
            *(float4*)&sS[row*P + c4] = *(const float4*)&sSp[row*P + c4];
        }
        chol64b(sS, dvec, invd);
        cho_solve_full(sS, invd, sY);                           // Y = Sp^-1 A Sf = G^T
        __syncthreads();

        if (tid < 64) {
            float acc = mfv[tid];
            for (int k = 0; k < 64; k++) acc += sY[k*P+tid] * dm[k];
            mus[tid] = acc;
        }
        mm64<0,true,true>(sD, sY, sSs, sSp, nullptr);           // D = Y^T (Ss - Sp) = G(Ss-Sp)
        __syncthreads();
        mm64<1,false,false>(sSs, sD, sY, nullptr, sSf);         // Ss = Sf + D Y
        __syncthreads();

        if (tid < 64) out_mq[base + tid] = mus[tid];
        for (int idx = tid; idx < 1024; idx += 256) {
            int row = idx >> 4, c4 = (idx & 15) * 4;
            *(float4*)&out_sq[base*64 + row*64 + c4] = *(const float4*)&sSs[row*P + c4];
        }
        __syncthreads();
    }
}

__global__ void __launch_bounds__(256, 1)
k_sample(const float* __restrict__ eps,
         const float* __restrict__ Wd, const float* __restrict__ bd,
         float* __restrict__ out) {
    __shared__ __align__(16) float sM[LAT*P];
    __shared__ float ev[64], zv[64], dvec[64], invd[64];
    int tok = blockIdx.x, tid = threadIdx.x;
    const float* sq = out + SQ_OFF + (size_t)tok * (LAT*LAT);
    const float* mq = out + MQ_OFF + tok * LAT;

    for (int idx = tid; idx < LAT*LAT; idx += 256) {
        int i = idx >> 6, j = idx & 63;
        sM[i*P+j] = sq[idx] + ((i == j) ? 1e-5f : 0.f);
    }
    if (tid < 64) ev[tid] = eps[tok*LAT + tid];
    chol64b(sM, dvec, invd);   // leading internal barrier covers the writes

    if (tid < 64) {
        float acc = mq[tid];
        for (int j = 0; j <= tid; j++) acc += sM[tid*P+j] * ev[j];
        zv[tid] = acc;
    }
    __syncthreads();
    if (tid < OBS) {
        float acc = bd[tid];
        for (int i = 0; i < 64; i++) acc += zv[i] * Wd[i*OBS + tid];
        out[XR_OFF + tok*OBS + tid] = acc;
    }
}

// ========================== launch ====================================

extern "C" void kernel_launch(void* const* d_in, const int* in_sizes, int n_in,
                              void* d_out, int out_size) {
    const float* x    = (const float*)d_in[0];
    const int*   mask = (const int*)  d_in[1];
    const float* eps  = (const float*)d_in[2];
    const float* W1   = (const float*)d_in[3];
    const float* b1   = (const float*)d_in[4];
    const float* Wm   = (const float*)d_in[5];
    const float* bm   = (const float*)d_in[6];
    const float* Wl   = (const float*)d_in[7];
    const float* bl   = (const float*)d_in[8];
    const float* Wd   = (const float*)d_in[9];
    const float* bd   = (const float*)d_in[10];
    const float* A    = (const float*)d_in[11];
    const float* bvec = (const float*)d_in[12];
    const float* Qp   = (const float*)d_in[13];
    float* out = (float*)d_out;

    k_buildQ <<<1, 256>>>(Qp);
    k_encoder<<<Bn*Tn, 128>>>(x, W1, b1, Wm, bm, Wl, bl);

    size_t smemF = (size_t)(8*LAT*P + 8*64 + 16) * sizeof(float);
    cudaFuncSetAttribute(k_filter, cudaFuncAttributeMaxDynamicSharedMemorySize, (int)smemF);
    k_filter<<<Bn, 256, smemF>>>(A, bvec, mask, out + LL_OFF);

    size_t smemS = (size_t)(9*LAT*P + 6*64 + 16) * sizeof(float);
    cudaFuncSetAttribute(k_smoother, cudaFuncAttributeMaxDynamicSharedMemorySize, (int)smemS);
    k_smoother<<<Bn, 256, smemS>>>(A, bvec, out);

    k_sample<<<Bn*Tn, 256>>>(eps, Wd, bd, out);
}

// round 8
// speedup vs baseline: 3.3668x; 1.8227x over previous
#include <cuda_runtime.h>
#include <math.h>

#define Bn 32
#define Tn 256
#define OBS 32
#define LAT 64
#define HID 400
#define P 68                      // pitch: %4==0 for float4
#define L2PI 1.8378770664093453f

#define XR_OFF 0
#define LL_OFF (Bn*Tn*OBS)
#define MQ_OFF (LL_OFF + Bn)
#define SQ_OFF (MQ_OFF + Bn*Tn*LAT)

__device__ float g_Q[LAT*LAT];
__device__ float g_zmu[Bn*Tn*LAT];
__device__ float g_sig[Bn*Tn*LAT];
__device__ float g_mf [Bn*Tn*LAT];
__device__ __align__(16) float g_Sf [(size_t)Bn*Tn*LAT*LAT];

// ---------------- f32x2 helpers ----------------
__device__ __forceinline__ unsigned long long pk2(float lo, float hi) {
    unsigned long long r;
    asm("mov.b64 %0, {%1,%2};" : "=l"(r) : "f"(lo), "f"(hi));
    return r;
}
__device__ __forceinline__ void upk2(unsigned long long v, float& lo, float& hi) {
    asm("mov.b64 {%0,%1}, %2;" : "=f"(lo), "=f"(hi) : "l"(v));
}
__device__ __forceinline__ void ffma2(unsigned long long& c, unsigned long long a, unsigned long long b) {
    asm("fma.rn.f32x2 %0, %1, %2, %0;" : "+l"(c) : "l"(a), "l"(b));
}

// ---------------- 64x64 matmul, 256 threads, 4x4 tiles, f32x2 ----------
#define MM_MICRO(A0,A1,A2,A3,BV) do{                                     \
    unsigned long long bp0 = pk2((BV).x,(BV).y), bp1 = pk2((BV).z,(BV).w);\
    unsigned long long d_;                                               \
    d_ = pk2(A0,A0); ffma2(acc[0][0],d_,bp0); ffma2(acc[0][1],d_,bp1);   \
    d_ = pk2(A1,A1); ffma2(acc[1][0],d_,bp0); ffma2(acc[1][1],d_,bp1);   \
    d_ = pk2(A2,A2); ffma2(acc[2][0],d_,bp0); ffma2(acc[2][1],d_,bp1);   \
    d_ = pk2(A3,A3); ffma2(acc[3][0],d_,bp0); ffma2(acc[3][1],d_,bp1);   \
}while(0)

template<int EPI, bool ATMODE, bool BDIFF>
__device__ __forceinline__ void mm64(float* C, const float* A, const float* B,
                                     const float* B2, const float* Add) {
    int tx = threadIdx.x & 15, ty = threadIdx.x >> 4;
    int i0 = 4*ty, j0 = 4*tx;
    unsigned long long acc[4][2];
#pragma unroll
    for (int i = 0; i < 4; i++) { acc[i][0] = 0ull; acc[i][1] = 0ull; }
#pragma unroll 2
    for (int kk = 0; kk < 64; kk += 4) {
        float4 b0 = *(const float4*)&B[(kk+0)*P + j0];
        float4 b1 = *(const float4*)&B[(kk+1)*P + j0];
        float4 b2 = *(const float4*)&B[(kk+2)*P + j0];
        float4 b3 = *(const float4*)&B[(kk+3)*P + j0];
        if (BDIFF) {
            float4 c0 = *(const float4*)&B2[(kk+0)*P + j0];
            float4 c1 = *(const float4*)&B2[(kk+1)*P + j0];
            float4 c2 = *(const float4*)&B2[(kk+2)*P + j0];
            float4 c3 = *(const float4*)&B2[(kk+3)*P + j0];
            b0.x-=c0.x; b0.y-=c0.y; b0.z-=c0.z; b0.w-=c0.w;
            b1.x-=c1.x; b1.y-=c1.y; b1.z-=c1.z; b1.w-=c1.w;
            b2.x-=c2.x; b2.y-=c2.y; b2.z-=c2.z; b2.w-=c2.w;
            b3.x-=c3.x; b3.y-=c3.y; b3.z-=c3.z; b3.w-=c3.w;
        }
        if (!ATMODE) {
            float4 a0 = *(const float4*)&A[(i0+0)*P + kk];
            float4 a1 = *(const float4*)&A[(i0+1)*P + kk];
            float4 a2 = *(const float4*)&A[(i0+2)*P + kk];
            float4 a3 = *(const float4*)&A[(i0+3)*P + kk];
            MM_MICRO(a0.x,a1.x,a2.x,a3.x, b0);
            MM_MICRO(a0.y,a1.y,a2.y,a3.y, b1);
            MM_MICRO(a0.z,a1.z,a2.z,a3.z, b2);
            MM_MICRO(a0.w,a1.w,a2.w,a3.w, b3);
        } else {
            float4 a0 = *(const float4*)&A[(kk+0)*P + i0];
            float4 a1 = *(const float4*)&A[(kk+1)*P + i0];
            float4 a2 = *(const float4*)&A[(kk+2)*P + i0];
            float4 a3 = *(const float4*)&A[(kk+3)*P + i0];
            MM_MICRO(a0.x,a0.y,a0.z,a0.w, b0);
            MM_MICRO(a1.x,a1.y,a1.z,a1.w, b1);
            MM_MICRO(a2.x,a2.y,a2.z,a2.w, b2);
            MM_MICRO(a3.x,a3.y,a3.z,a3.w, b3);
        }
    }
#pragma unroll
    for (int i = 0; i < 4; i++) {
        float v0,v1,v2,v3;
        upk2(acc[i][0], v0, v1);
        upk2(acc[i][1], v2, v3);
        float4 r;
        if (EPI == 0) r = make_float4(v0,v1,v2,v3);
        else {
            float4 ad = *(const float4*)&Add[(i0+i)*P + j0];
            if (EPI == 1) r = make_float4(ad.x+v0, ad.y+v1, ad.z+v2, ad.w+v3);
            else          r = make_float4(ad.x-v0, ad.y-v1, ad.z-v2, ad.w-v3);
        }
        *(float4*)&C[(i0+i)*P + j0] = r;
    }
}

// ---- fused Joseph: C = M1 + (K*diag(rd) - M1) @ K^T  (all row-major) ----
__device__ __forceinline__ void jos64f(float* C, const float* M1, const float* K,
                                       const float* rd) {
    int tx = threadIdx.x & 15, ty = threadIdx.x >> 4;
    int i0 = 4*ty, j0 = 4*tx;
    unsigned long long acc[4][4];
#pragma unroll
    for (int i = 0; i < 4; i++)
#pragma unroll
        for (int j = 0; j < 4; j++) acc[i][j] = 0ull;
    for (int kk = 0; kk < 64; kk += 4) {
        float4 rv = *(const float4*)&rd[kk];
        float4 lj[4];
#pragma unroll
        for (int c = 0; c < 4; c++) lj[c] = *(const float4*)&K[(j0+c)*P + kk];
        unsigned long long ljp[4][2];
#pragma unroll
        for (int c = 0; c < 4; c++) {
            ljp[c][0] = pk2(lj[c].x, lj[c].y);
            ljp[c][1] = pk2(lj[c].z, lj[c].w);
        }
#pragma unroll
        for (int i = 0; i < 4; i++) {
            float4 tk = *(const float4*)&K [(i0+i)*P + kk];
            float4 tm = *(const float4*)&M1[(i0+i)*P + kk];
            float4 t;
            t.x = tk.x*rv.x - tm.x;
            t.y = tk.y*rv.y - tm.y;
            t.z = tk.z*rv.z - tm.z;
            t.w = tk.w*rv.w - tm.w;
            unsigned long long t01 = pk2(t.x, t.y), t23 = pk2(t.z, t.w);
#pragma unroll
            for (int c = 0; c < 4; c++) {
                ffma2(acc[i][c], t01, ljp[c][0]);
                ffma2(acc[i][c], t23, ljp[c][1]);
            }
        }
    }
#pragma unroll
    for (int i = 0; i < 4; i++) {
        float4 m = *(const float4*)&M1[(i0+i)*P + j0];
        float lo, hi, v[4];
#pragma unroll
        for (int c = 0; c < 4; c++) { upk2(acc[i][c], lo, hi); v[c] = lo + hi; }
        float4 r = make_float4(m.x+v[0], m.y+v[1], m.z+v[2], m.w+v[3]);
        *(float4*)&C[(i0+i)*P + j0] = r;
    }
}

// ---------------- blocked Cholesky 64x64, panel=8, 256 threads ----------
__device__ void chol64b(float* M, float* dvec, float* invd) {
    const int tid = threadIdx.x;
    const int tx = tid & 15, ty = tid >> 4;
    const int i0 = 4*ty, j0 = 4*tx;
    for (int p = 0; p < 64; p += 8) {
        for (int k = p; k < p + 8; k++) {
            __syncthreads();
            float iv2 = 1.0f / fmaxf(M[k*P+k], 1e-20f);
            int idx = tid;
#pragma unroll
            for (int rr = 0; rr < 2; rr++, idx += 256) {
                int i = idx >> 3, j = p + (idx & 7);
                if (i > k && j > k && j <= i)
                    M[i*P+j] -= M[i*P+k] * M[j*P+k] * iv2;
            }
        }
        __syncthreads();
        if (tid < 8) {
            int i = p + tid;
            float d = sqrtf(fmaxf(M[i*P+i], 1e-20f));
            dvec[i] = d;
            invd[i] = 1.0f / d;
        }
        __syncthreads();
        {
            int idx = tid;
#pragma unroll
            for (int rr = 0; rr < 2; rr++, idx += 256) {
                int i = idx >> 3, j = p + (idx & 7);
                if (j < i)       M[i*P+j] *= invd[j];
                else if (j == i) M[i*P+i]  = dvec[i];
            }
        }
        __syncthreads();
        if (p + 8 < 64 && i0 >= p + 8 && j0 >= p + 8) {
            float4 lj[4][2];
#pragma unroll
            for (int c = 0; c < 4; c++) {
                lj[c][0] = *(const float4*)&M[(j0+c)*P + p];
                lj[c][1] = *(const float4*)&M[(j0+c)*P + p + 4];
            }
#pragma unroll
            for (int r = 0; r < 4; r++) {
                float4 li0 = *(const float4*)&M[(i0+r)*P + p];
                float4 li1 = *(const float4*)&M[(i0+r)*P + p + 4];
                float4 mr  = *(const float4*)&M[(i0+r)*P + j0];
                float s0 = li0.x*lj[0][0].x + li0.y*lj[0][0].y + li0.z*lj[0][0].z + li0.w*lj[0][0].w
                         + li1.x*lj[0][1].x + li1.y*lj[0][1].y + li1.z*lj[0][1].z + li1.w*lj[0][1].w;
                float s1 = li0.x*lj[1][0].x + li0.y*lj[1][0].y + li0.z*lj[1][0].z + li0.w*lj[1][0].w
                         + li1.x*lj[1][1].x + li1.y*lj[1][1].y + li1.z*lj[1][1].z + li1.w*lj[1][1].w;
                float s2 = li0.x*lj[2][0].x + li0.y*lj[2][0].y + li0.z*lj[2][0].z + li0.w*lj[2][0].w
                         + li1.x*lj[2][1].x + li1.y*lj[2][1].y + li1.z*lj[2][1].z + li1.w*lj[2][1].w;
                float s3 = li0.x*lj[3][0].x + li0.y*lj[3][0].y + li0.z*lj[3][0].z + li0.w*lj[3][0].w
                         + li1.x*lj[3][1].x + li1.y*lj[3][1].y + li1.z*lj[3][1].z + li1.w*lj[3][1].w;
                mr.x -= s0; mr.y -= s1; mr.z -= s2; mr.w -= s3;
                *(float4*)&M[(i0+r)*P + j0] = mr;
            }
        }
    }
    __syncthreads();
}

// ---------------- blocked triangular inverse: T = L^-1 -------------------
// L in sL (lower + diag valid, pitch P), invd = 1/diag(L). T zero-filled and
// written dense (upper = 0). U: 512-float smem scratch. 256 threads.
__device__ void trinv64(const float* L, const float* invd, float* T, float* U) {
    const int tid = threadIdx.x;
    for (int e = tid; e < 64*P; e += 256) T[e] = 0.f;
    __syncthreads();
    if (tid < 64) {                       // 8 diag blocks in parallel
        int I = tid >> 3, j = tid & 7;
        int base = 8*I;
        float x[8];
#pragma unroll
        for (int r = 0; r < 8; r++) {
            float acc = (r == j) ? 1.f : 0.f;
#pragma unroll
            for (int s = 0; s < 8; s++)
                if (s < r) acc -= L[(base+r)*P + base + s] * x[s];
            x[r] = (r < j) ? 0.f : acc * invd[base + r];
        }
#pragma unroll
        for (int r = 0; r < 8; r++) T[(base+r)*P + base + j] = x[r];
    }
    __syncthreads();
    for (int d = 1; d < 8; d++) {
        int nblk = 8 - d;
        for (int e = tid; e < nblk*64; e += 256) {     // stage 1: U = L[I,J..I) @ T[J..I, J]
            int blk = e >> 6, rc = e & 63;
            int r = rc >> 3, c = rc & 7;
            int I = blk + d, J = blk;
            int row = 8*I + r;
            float acc = 0.f;
            for (int k = 8*J; k < 8*I; k++)
                acc += L[row*P + k] * T[k*P + 8*J + c];
            U[e] = acc;
        }
        __syncthreads();
        for (int e = tid; e < nblk*64; e += 256) {     // stage 2: T[I,J] = -T[I,I] @ U
            int blk = e >> 6, rc = e & 63;
            int r = rc >> 3, c = rc & 7;
            int I = blk + d, J = blk;
            int row = 8*I + r;
            float acc = 0.f;
#pragma unroll
            for (int m = 0; m < 8; m++)
                acc -= T[row*P + 8*I + m] * U[blk*64 + m*8 + c];
            T[row*P + 8*J + c] = acc;
        }
        __syncthreads();
    }
}

// ========================== kernels ====================================

__global__ void k_buildQ(const float* __restrict__ qp) {
    __shared__ float sL[LAT*P];
    int tid = threadIdx.x;
    for (int idx = tid; idx < LAT*LAT; idx += blockDim.x) {
        int i = idx >> 6, j = idx & 63;
        float v = 0.f;
        if (j <= i) { v = qp[i*(i+1)/2 + j]; if (j == i) v = expf(v); }
        sL[i*P+j] = v;
    }
    __syncthreads();
    for (int idx = tid; idx < LAT*LAT; idx += blockDim.x) {
        int i = idx >> 6, j = idx & 63;
        int m = i < j ? i : j;
        float acc = 0.f;
        for (int k = 0; k <= m; k++) acc += sL[i*P+k] * sL[j*P+k];
        g_Q[idx] = acc;
    }
}

__global__ void k_encoder(const float* __restrict__ x,
                          const float* __restrict__ W1, const float* __restrict__ b1,
                          const float* __restrict__ Wm, const float* __restrict__ bm,
                          const float* __restrict__ Wl, const float* __restrict__ bl) {
    __shared__ float xs[OBS];
    __shared__ float h[HID];
    int tok = blockIdx.x, tid = threadIdx.x;
    if (tid < OBS) xs[tid] = x[tok*OBS + tid];
    __syncthreads();
    for (int j = tid; j < HID; j += blockDim.x) {
        float acc = b1[j];
#pragma unroll
        for (int k = 0; k < OBS; k++) acc += xs[k] * W1[k*HID + j];
        h[j] = fmaxf(acc, 0.f);
    }
    __syncthreads();
    if (tid < LAT) {
        float acc = bm[tid];
        for (int j = 0; j < HID; j++) acc += h[j] * Wm[j*LAT + tid];
        g_zmu[tok*LAT + tid] = acc;
    } else if (tid < 2*LAT) {
        int o = tid - LAT;
        float acc = bl[o];
        for (int j = 0; j < HID; j++) acc += h[j] * Wl[j*LAT + o];
        g_sig[tok*LAT + o] = expf(0.5f * acc);
    }
}

__global__ void __launch_bounds__(256, 1)
k_filter(const float* __restrict__ Amat, const float* __restrict__ bvec_g,
         const int* __restrict__ mask, float* __restrict__ out_ll) {
    extern __shared__ float sm[];
    float* sA   = sm;
    float* sAT  = sA   + LAT*P;
    float* sQ   = sAT  + LAT*P;
    float* sSig = sQ   + LAT*P;
    float* sT1  = sSig + LAT*P;
    float* sSp  = sT1  + LAT*P;
    float* sS   = sSp  + LAT*P;
    float* sK   = sS   + LAT*P;
    float* sT   = sK   + LAT*P;
    float* sZ   = sT   + LAT*P;
    float* vb   = sZ   + LAT*P;
    float* mu    = vb;          float* mup  = mu    + 64;
    float* r     = mup  + 64;   float* rd   = r     + 64;
    float* bv    = rd   + 64;   float* dvec = bv    + 64;
    float* invd  = dvec + 64;   float* scal = invd  + 64;  // [0..2]
    float* psq   = scal + 8;    float* plg  = psq   + 4;
    float* sU    = plg  + 4;    // 512 floats

    int b = blockIdx.x, tid = threadIdx.x;

    for (int idx = tid; idx < LAT*LAT; idx += 256) {
        int i = idx >> 6, j = idx & 63;
        float a = Amat[idx];
        sA [i*P+j] = a;
        sAT[j*P+i] = a;
        sQ [i*P+j] = g_Q[idx];
        sSig[i*P+j] = (i == j) ? 1.f : 0.f;
    }
    if (tid < 64) { mu[tid] = 0.f; bv[tid] = bvec_g[tid]; }
    if (tid == 0) scal[2] = 0.f;
    __syncthreads();

    for (int t = 0; t < Tn; t++) {
        int base = (b*Tn + t) * LAT;
        int m = mask[b*Tn + t];

        if (tid < 64) {
            float acc = bv[tid];
            for (int k = 0; k < 64; k++) acc += sAT[k*P+tid] * mu[k];
            mup[tid] = acc;
            r[tid]   = g_zmu[base + tid] - acc;
            rd[tid]  = g_sig[base + tid];
        }
        __syncthreads();

        mm64<0,false,false>(sT1, sA, sSig, nullptr, nullptr);   // T1 = A Sig
        __syncthreads();
        mm64<1,false,false>(sSp, sT1, sAT, nullptr, sQ);        // Sp = T1 A^T + Q
        __syncthreads();

        if (m) {
            if (tid < 64) mu[tid] = mup[tid];
            for (int idx = tid; idx < 1024; idx += 256) {
                int row = idx >> 4, c4 = (idx & 15) * 4;
                *(float4*)&sSig[row*P + c4] = *(const float4*)&sSp[row*P + c4];
            }
        } else {
            for (int idx = tid; idx < 4096; idx += 256) {
                int i = idx >> 6, j = idx & 63;
                float v = sSp[i*P+j];
                if (i == j) v += rd[i];
                sS[i*P+j] = v;
            }
            chol64b(sS, dvec, invd);                 // L in sS (+ its final barrier)
            trinv64(sS, invd, sT, sU);               // T = L^-1 (+ its final barrier)

            mm64<0,false,false>(sZ, sT, sSp, nullptr, nullptr);  // Z = T Sp
            if (tid < 64) {                          // alpha = T r ; log pivots
                float a = 0.f;
                for (int k = 0; k < 64; k++) a += sT[tid*P+k] * r[k];
                float sq = a * a;
                float lg = logf(dvec[tid]);
#pragma unroll
                for (int o = 16; o; o >>= 1) {
                    sq += __shfl_xor_sync(0xffffffffu, sq, o);
                    lg += __shfl_xor_sync(0xffffffffu, lg, o);
                }
                if ((tid & 31) == 0) { psq[tid>>5] = sq; plg[tid>>5] = lg; }
            }
            __syncthreads();

            mm64<0,true,false>(sK, sZ, sT, nullptr, nullptr);    // K = Z^T T
            __syncthreads();

            if (tid < 64) {
                float acc = mup[tid];
                for (int k = 0; k < 64; k++) acc += sK[tid*P+k] * r[k];
                mu[tid] = acc;
            }
            if (tid == 64)
                scal[2] += -0.5f * 64.f * L2PI - (plg[0]+plg[1]) - 0.5f * (psq[0]+psq[1]);
            mm64<2,false,false>(sT1, sK, sSp, nullptr, sSp);     // M1 = Sp - K Sp
            __syncthreads();
            jos64f(sSig, sT1, sK, rd);                           // Joseph form
        }
        __syncthreads();

        if (tid < 64) g_mf[base + tid] = mu[tid];
        for (int idx = tid; idx < 1024; idx += 256) {
            int row = idx >> 4, c4 = (idx & 15) * 4;
            *(float4*)&g_Sf[(size_t)base*64 + row*64 + c4] =
                *(const float4*)&sSig[row*P + c4];
        }
        __syncthreads();
    }
    if (tid == 0) out_ll[b] = scal[2];
}

__global__ void __launch_bounds__(256, 1)
k_smoother(const float* __restrict__ Amat, const float* __restrict__ bvec_g,
           float* __restrict__ out) {
    extern __shared__ float sm[];
    float* sA   = sm;
    float* sAT  = sA   + LAT*P;
    float* sQ   = sAT  + LAT*P;
    float* sSf  = sQ   + LAT*P;
    float* sSs  = sSf  + LAT*P;
    float* sY   = sSs  + LAT*P;
    float* sSp  = sY   + LAT*P;
    float* sS   = sSp  + LAT*P;
    float* sT   = sS   + LAT*P;
    float* sZ   = sT   + LAT*P;   // also reused as D
    float* vb   = sZ   + LAT*P;
    float* mfv    = vb;          float* mus  = mfv    + 64;
    float* dm     = mus  + 64;   float* bv   = dm     + 64;
    float* dvec   = bv   + 64;   float* invd = dvec   + 64;
    float* sU     = invd + 64;   // 512 floats

    int b = blockIdx.x, tid = threadIdx.x;
    float* out_mq = out + MQ_OFF;
    float* out_sq = out + SQ_OFF;

    for (int idx = tid; idx < LAT*LAT; idx += 256) {
        int i = idx >> 6, j = idx & 63;
        float a = Amat[idx];
        sA [i*P+j] = a;
        sAT[j*P+i] = a;
        sQ [i*P+j] = g_Q[idx];
    }
    size_t baseT = ((size_t)b*Tn + (Tn-1)) * LAT;
    if (tid < 64) {
        mus[tid] = g_mf[baseT + tid];
        bv[tid]  = bvec_g[tid];
        out_mq[baseT + tid] = mus[tid];
    }
    for (int idx = tid; idx < 1024; idx += 256) {
        int row = idx >> 4, c4 = (idx & 15) * 4;
        float4 v = *(const float4*)&g_Sf[baseT*64 + row*64 + c4];
        *(float4*)&sSs[row*P + c4] = v;
        *(float4*)&out_sq[baseT*64 + row*64 + c4] = v;
    }
    __syncthreads();

    for (int t = Tn - 2; t >= 0; t--) {
        size_t base = ((size_t)b*Tn + t) * LAT;
        if (tid < 64) mfv[tid] = g_mf[base + tid];
        for (int idx = tid; idx < 1024; idx += 256) {
            int row = idx >> 4, c4 = (idx & 15) * 4;
            *(float4*)&sSf[row*P + c4] = *(const float4*)&g_Sf[base*64 + row*64 + c4];
        }
        __syncthreads();

        if (tid < 64) {
            float acc = bv[tid];
            for (int k = 0; k < 64; k++) acc += sAT[k*P+tid] * mfv[k];
            dm[tid] = mus[tid] - acc;
        }
        __syncthreads();

        mm64<0,false,false>(sY, sA, sSf, nullptr, nullptr);     // Y0 = A Sf
        __syncthreads();
        mm64<1,false,false>(sSp, sY, sAT, nullptr, sQ);         // Sp = Y0 A^T + Q
        __syncthreads();
        for (int idx = tid; idx < 1024; idx += 256) {
            int row = idx >> 4, c4 = (idx & 15) * 4;
            *(float4*)&sS[row*P + c4] = *(const float4*)&sSp[row*P + c4];
        }
        chol64b(sS, dvec, invd);
        trinv64(sS, invd, sT, sU);                              // T = L^-1

        mm64<0,false,false>(sZ, sT, sY, nullptr, nullptr);      // Z = T Y0
        __syncthreads();
        mm64<0,true,false>(sY, sT, sZ, nullptr, nullptr);       // Y = T^T Z = Sp^-1 A Sf = G^T
        __syncthreads();

        if (tid < 64) {
            float acc = mfv[tid];
            for (int k = 0; k < 64; k++) acc += sY[k*P+tid] * dm[k];
            mus[tid] = acc;
        }
        mm64<0,true,true>(sZ, sY, sSs, sSp, nullptr);           // D = Y^T (Ss - Sp)
        __syncthreads();
        mm64<1,false,false>(sSs, sZ, sY, nullptr, sSf);         // Ss = Sf + D Y
        __syncthreads();

        if (tid < 64) out_mq[base + tid] = mus[tid];
        for (int idx = tid; idx < 1024; idx += 256) {
            int row = idx >> 4, c4 = (idx & 15) * 4;
            *(float4*)&out_sq[base*64 + row*64 + c4] = *(const float4*)&sSs[row*P + c4];
        }
        __syncthreads();
    }
}

__global__ void __launch_bounds__(256, 1)
k_sample(const float* __restrict__ eps,
         const float* __restrict__ Wd, const float* __restrict__ bd,
         float* __restrict__ out) {
    __shared__ __align__(16) float sM[LAT*P];
    __shared__ float ev[64], zv[64], dvec[64], invd[64];
    int tok = blockIdx.x, tid = threadIdx.x;
    const float* sq = out + SQ_OFF + (size_t)tok * (LAT*LAT);
    const float* mq = out + MQ_OFF + tok * LAT;

    for (int idx = tid; idx < LAT*LAT; idx += 256) {
        int i = idx >> 6, j = idx & 63;
        sM[i*P+j] = sq[idx] + ((i == j) ? 1e-5f : 0.f);
    }
    if (tid < 64) ev[tid] = eps[tok*LAT + tid];
    chol64b(sM, dvec, invd);   // leading internal barrier covers the writes

    if (tid < 64) {
        float acc = mq[tid];
        for (int j = 0; j <= tid; j++) acc += sM[tid*P+j] * ev[j];
        zv[tid] = acc;
    }
    __syncthreads();
    if (tid < OBS) {
        float acc = bd[tid];
        for (int i = 0; i < 64; i++) acc += zv[i] * Wd[i*OBS + tid];
        out[XR_OFF + tok*OBS + tid] = acc;
    }
}

// ========================== launch ====================================

extern "C" void kernel_launch(void* const* d_in, const int* in_sizes, int n_in,
                              void* d_out, int out_size) {
    const float* x    = (const float*)d_in[0];
    const int*   mask = (const int*)  d_in[1];
    const float* eps  = (const float*)d_in[2];
    const float* W1   = (const float*)d_in[3];
    const float* b1   = (const float*)d_in[4];
    const float* Wm   = (const float*)d_in[5];
    const float* bm   = (const float*)d_in[6];
    const float* Wl   = (const float*)d_in[7];
    const float* bl   = (const float*)d_in[8];
    const float* Wd   = (const float*)d_in[9];
    const float* bd   = (const float*)d_in[10];
    const float* A    = (const float*)d_in[11];
    const float* bvec = (const float*)d_in[12];
    const float* Qp   = (const float*)d_in[13];
    float* out = (float*)d_out;

    k_buildQ <<<1, 256>>>(Qp);
    k_encoder<<<Bn*Tn, 128>>>(x, W1, b1, Wm, bm, Wl, bl);

    size_t smemF = (size_t)(10*LAT*P + 8*64 + 16 + 512) * sizeof(float);
    cudaFuncSetAttribute(k_filter, cudaFuncAttributeMaxDynamicSharedMemorySize, (int)smemF);
    k_filter<<<Bn, 256, smemF>>>(A, bvec, mask, out + LL_OFF);

    size_t smemS = (size_t)(10*LAT*P + 6*64 + 512) * sizeof(float);
    cudaFuncSetAttribute(k_smoother, cudaFuncAttributeMaxDynamicSharedMemorySize, (int)smemS);
    k_smoother<<<Bn, 256, smemS>>>(A, bvec, out);

    k_sample<<<Bn*Tn, 256>>>(eps, Wd, bd, out);
}

// round 9
// speedup vs baseline: 3.3758x; 1.0027x over previous
#include <cuda_runtime.h>
#include <math.h>

#define Bn 32
#define Tn 256
#define OBS 32
#define LAT 64
#define HID 400
#define P 68                      // pitch: %4==0 for float4
#define L2PI 1.8378770664093453f

#define XR_OFF 0
#define LL_OFF (Bn*Tn*OBS)
#define MQ_OFF (LL_OFF + Bn)
#define SQ_OFF (MQ_OFF + Bn*Tn*LAT)

__device__ float g_Q[LAT*LAT];
__device__ float g_zmu[Bn*Tn*LAT];
__device__ float g_sig[Bn*Tn*LAT];
__device__ float g_mf [Bn*Tn*LAT];
__device__ __align__(16) float g_Sf [(size_t)Bn*Tn*LAT*LAT];

// ---------------- f32x2 helpers ----------------
__device__ __forceinline__ unsigned long long pk2(float lo, float hi) {
    unsigned long long r;
    asm("mov.b64 %0, {%1,%2};" : "=l"(r) : "f"(lo), "f"(hi));
    return r;
}
__device__ __forceinline__ void upk2(unsigned long long v, float& lo, float& hi) {
    asm("mov.b64 {%0,%1}, %2;" : "=f"(lo), "=f"(hi) : "l"(v));
}
__device__ __forceinline__ void ffma2(unsigned long long& c, unsigned long long a, unsigned long long b) {
    asm("fma.rn.f32x2 %0, %1, %2, %0;" : "+l"(c) : "l"(a), "l"(b));
}

// ---------------- 64x64 matmul, 256 threads, 4x4 tiles, f32x2 ----------
#define MM_MICRO(A0,A1,A2,A3,BV) do{                                     \
    unsigned long long bp0 = pk2((BV).x,(BV).y), bp1 = pk2((BV).z,(BV).w);\
    unsigned long long d_;                                               \
    d_ = pk2(A0,A0); ffma2(acc[0][0],d_,bp0); ffma2(acc[0][1],d_,bp1);   \
    d_ = pk2(A1,A1); ffma2(acc[1][0],d_,bp0); ffma2(acc[1][1],d_,bp1);   \
    d_ = pk2(A2,A2); ffma2(acc[2][0],d_,bp0); ffma2(acc[2][1],d_,bp1);   \
    d_ = pk2(A3,A3); ffma2(acc[3][0],d_,bp0); ffma2(acc[3][1],d_,bp1);   \
}while(0)

template<int EPI, bool ATMODE, bool BDIFF>
__device__ __forceinline__ void mm64(float* C, const float* A, const float* B,
                                     const float* B2, const float* Add) {
    int tx = threadIdx.x & 15, ty = threadIdx.x >> 4;
    int i0 = 4*ty, j0 = 4*tx;
    unsigned long long acc[4][2];
#pragma unroll
    for (int i = 0; i < 4; i++) { acc[i][0] = 0ull; acc[i][1] = 0ull; }
#pragma unroll 2
    for (int kk = 0; kk < 64; kk += 4) {
        float4 b0 = *(const float4*)&B[(kk+0)*P + j0];
        float4 b1 = *(const float4*)&B[(kk+1)*P + j0];
        float4 b2 = *(const float4*)&B[(kk+2)*P + j0];
        float4 b3 = *(const float4*)&B[(kk+3)*P + j0];
        if (BDIFF) {
            float4 c0 = *(const float4*)&B2[(kk+0)*P + j0];
            float4 c1 = *(const float4*)&B2[(kk+1)*P + j0];
            float4 c2 = *(const float4*)&B2[(kk+2)*P + j0];
            float4 c3 = *(const float4*)&B2[(kk+3)*P + j0];
            b0.x-=c0.x; b0.y-=c0.y; b0.z-=c0.z; b0.w-=c0.w;
            b1.x-=c1.x; b1.y-=c1.y; b1.z-=c1.z; b1.w-=c1.w;
            b2.x-=c2.x; b2.y-=c2.y; b2.z-=c2.z; b2.w-=c2.w;
            b3.x-=c3.x; b3.y-=c3.y; b3.z-=c3.z; b3.w-=c3.w;
        }
        if (!ATMODE) {
            float4 a0 = *(const float4*)&A[(i0+0)*P + kk];
            float4 a1 = *(const float4*)&A[(i0+1)*P + kk];
            float4 a2 = *(const float4*)&A[(i0+2)*P + kk];
            float4 a3 = *(const float4*)&A[(i0+3)*P + kk];
            MM_MICRO(a0.x,a1.x,a2.x,a3.x, b0);
            MM_MICRO(a0.y,a1.y,a2.y,a3.y, b1);
            MM_MICRO(a0.z,a1.z,a2.z,a3.z, b2);
            MM_MICRO(a0.w,a1.w,a2.w,a3.w, b3);
        } else {
            float4 a0 = *(const float4*)&A[(kk+0)*P + i0];
            float4 a1 = *(const float4*)&A[(kk+1)*P + i0];
            float4 a2 = *(const float4*)&A[(kk+2)*P + i0];
            float4 a3 = *(const float4*)&A[(kk+3)*P + i0];
            MM_MICRO(a0.x,a0.y,a0.z,a0.w, b0);
            MM_MICRO(a1.x,a1.y,a1.z,a1.w, b1);
            MM_MICRO(a2.x,a2.y,a2.z,a2.w, b2);
            MM_MICRO(a3.x,a3.y,a3.z,a3.w, b3);
        }
    }
#pragma unroll
    for (int i = 0; i < 4; i++) {
        float v0,v1,v2,v3;
        upk2(acc[i][0], v0, v1);
        upk2(acc[i][1], v2, v3);
        float4 r;
        if (EPI == 0) r = make_float4(v0,v1,v2,v3);
        else {
            float4 ad = *(const float4*)&Add[(i0+i)*P + j0];
            if (EPI == 1) r = make_float4(ad.x+v0, ad.y+v1, ad.z+v2, ad.w+v3);
            else          r = make_float4(ad.x-v0, ad.y-v1, ad.z-v2, ad.w-v3);
        }
        *(float4*)&C[(i0+i)*P + j0] = r;
    }
}

// ---- fused Joseph: C = M1 + (K*diag(rd) - M1) @ K^T  (all row-major) ----
__device__ __forceinline__ void jos64f(float* C, const float* M1, const float* K,
                                       const float* rd) {
    int tx = threadIdx.x & 15, ty = threadIdx.x >> 4;
    int i0 = 4*ty, j0 = 4*tx;
    unsigned long long acc[4][4];
#pragma unroll
    for (int i = 0; i < 4; i++)
#pragma unroll
        for (int j = 0; j < 4; j++) acc[i][j] = 0ull;
    for (int kk = 0; kk < 64; kk += 4) {
        float4 rv = *(const float4*)&rd[kk];
        float4 lj[4];
#pragma unroll
        for (int c = 0; c < 4; c++) lj[c] = *(const float4*)&K[(j0+c)*P + kk];
        unsigned long long ljp[4][2];
#pragma unroll
        for (int c = 0; c < 4; c++) {
            ljp[c][0] = pk2(lj[c].x, lj[c].y);
            ljp[c][1] = pk2(lj[c].z, lj[c].w);
        }
#pragma unroll
        for (int i = 0; i < 4; i++) {
            float4 tk = *(const float4*)&K [(i0+i)*P + kk];
            float4 tm = *(const float4*)&M1[(i0+i)*P + kk];
            float4 t;
            t.x = tk.x*rv.x - tm.x;
            t.y = tk.y*rv.y - tm.y;
            t.z = tk.z*rv.z - tm.z;
            t.w = tk.w*rv.w - tm.w;
            unsigned long long t01 = pk2(t.x, t.y), t23 = pk2(t.z, t.w);
#pragma unroll
            for (int c = 0; c < 4; c++) {
                ffma2(acc[i][c], t01, ljp[c][0]);
                ffma2(acc[i][c], t23, ljp[c][1]);
            }
        }
    }
#pragma unroll
    for (int i = 0; i < 4; i++) {
        float4 m = *(const float4*)&M1[(i0+i)*P + j0];
        float lo, hi, v[4];
#pragma unroll
        for (int c = 0; c < 4; c++) { upk2(acc[i][c], lo, hi); v[c] = lo + hi; }
        float4 r = make_float4(m.x+v[0], m.y+v[1], m.z+v[2], m.w+v[3]);
        *(float4*)&C[(i0+i)*P + j0] = r;
    }
}

// ---------------- blocked Cholesky 64x64, panel=8, 256 threads ----------
__device__ void chol64b(float* M, float* dvec, float* invd) {
    const int tid = threadIdx.x;
    const int tx = tid & 15, ty = tid >> 4;
    const int i0 = 4*ty, j0 = 4*tx;
    for (int p = 0; p < 64; p += 8) {
        for (int k = p; k < p + 8; k++) {
            __syncthreads();
            float iv2 = 1.0f / fmaxf(M[k*P+k], 1e-20f);
            int idx = tid;
#pragma unroll
            for (int rr = 0; rr < 2; rr++, idx += 256) {
                int i = idx >> 3, j = p + (idx & 7);
                if (i > k && j > k && j <= i)
                    M[i*P+j] -= M[i*P+k] * M[j*P+k] * iv2;
            }
        }
        __syncthreads();
        if (tid < 8) {
            int i = p + tid;
            float d = sqrtf(fmaxf(M[i*P+i], 1e-20f));
            dvec[i] = d;
            invd[i] = 1.0f / d;
        }
        __syncthreads();
        {
            int idx = tid;
#pragma unroll
            for (int rr = 0; rr < 2; rr++, idx += 256) {
                int i = idx >> 3, j = p + (idx & 7);
                if (j < i)       M[i*P+j] *= invd[j];
                else if (j == i) M[i*P+i]  = dvec[i];
            }
        }
        __syncthreads();
        if (p + 8 < 64 && i0 >= p + 8 && j0 >= p + 8) {
            float4 lj[4][2];
#pragma unroll
            for (int c = 0; c < 4; c++) {
                lj[c][0] = *(const float4*)&M[(j0+c)*P + p];
                lj[c][1] = *(const float4*)&M[(j0+c)*P + p + 4];
            }
#pragma unroll
            for (int r = 0; r < 4; r++) {
                float4 li0 = *(const float4*)&M[(i0+r)*P + p];
                float4 li1 = *(const float4*)&M[(i0+r)*P + p + 4];
                float4 mr  = *(const float4*)&M[(i0+r)*P + j0];
                float s0 = li0.x*lj[0][0].x + li0.y*lj[0][0].y + li0.z*lj[0][0].z + li0.w*lj[0][0].w
                         + li1.x*lj[0][1].x + li1.y*lj[0][1].y + li1.z*lj[0][1].z + li1.w*lj[0][1].w;
                float s1 = li0.x*lj[1][0].x + li0.y*lj[1][0].y + li0.z*lj[1][0].z + li0.w*lj[1][0].w
                         + li1.x*lj[1][1].x + li1.y*lj[1][1].y + li1.z*lj[1][1].z + li1.w*lj[1][1].w;
                float s2 = li0.x*lj[2][0].x + li0.y*lj[2][0].y + li0.z*lj[2][0].z + li0.w*lj[2][0].w
                         + li1.x*lj[2][1].x + li1.y*lj[2][1].y + li1.z*lj[2][1].z + li1.w*lj[2][1].w;
                float s3 = li0.x*lj[3][0].x + li0.y*lj[3][0].y + li0.z*lj[3][0].z + li0.w*lj[3][0].w
                         + li1.x*lj[3][1].x + li1.y*lj[3][1].y + li1.z*lj[3][1].z + li1.w*lj[3][1].w;
                mr.x -= s0; mr.y -= s1; mr.z -= s2; mr.w -= s3;
                *(float4*)&M[(i0+r)*P + j0] = mr;
            }
        }
    }
    __syncthreads();
}

// ---------------- blocked triangular inverse: T = L^-1 -------------------
// L in sL (lower + diag valid, pitch P), invd = 1/diag(L). T zero-filled and
// written dense (upper = 0). U: 512-float smem scratch. 256 threads.
__device__ void trinv64(const float* L, const float* invd, float* T, float* U) {
    const int tid = threadIdx.x;
    for (int e = tid; e < 64*P; e += 256) T[e] = 0.f;
    __syncthreads();
    if (tid < 64) {                       // 8 diag blocks in parallel
        int I = tid >> 3, j = tid & 7;
        int base = 8*I;
        float x[8];
#pragma unroll
        for (int r = 0; r < 8; r++) {
            float acc = (r == j) ? 1.f : 0.f;
#pragma unroll
            for (int s = 0; s < 8; s++)
                if (s < r) acc -= L[(base+r)*P + base + s] * x[s];
            x[r] = (r < j) ? 0.f : acc * invd[base + r];
        }
#pragma unroll
        for (int r = 0; r < 8; r++) T[(base+r)*P + base + j] = x[r];
    }
    __syncthreads();
    for (int d = 1; d < 8; d++) {
        int nblk = 8 - d;
        for (int e = tid; e < nblk*64; e += 256) {     // stage 1: U = L[I,J..I) @ T[J..I, J]
            int blk = e >> 6, rc = e & 63;
            int r = rc >> 3, c = rc & 7;
            int I = blk + d, J = blk;
            int row = 8*I + r;
            float acc = 0.f;
            for (int k = 8*J; k < 8*I; k++)
                acc += L[row*P + k] * T[k*P + 8*J + c];
            U[e] = acc;
        }
        __syncthreads();
        for (int e = tid; e < nblk*64; e += 256) {     // stage 2: T[I,J] = -T[I,I] @ U
            int blk = e >> 6, rc = e & 63;
            int r = rc >> 3, c = rc & 7;
            int I = blk + d, J = blk;
            int row = 8*I + r;
            float acc = 0.f;
#pragma unroll
            for (int m = 0; m < 8; m++)
                acc -= T[row*P + 8*I + m] * U[blk*64 + m*8 + c];
            T[row*P + 8*J + c] = acc;
        }
        __syncthreads();
    }
}

// ========================== kernels ====================================

__global__ void k_buildQ(const float* __restrict__ qp) {
    __shared__ float sL[LAT*P];
    int tid = threadIdx.x;
    for (int idx = tid; idx < LAT*LAT; idx += blockDim.x) {
        int i = idx >> 6, j = idx & 63;
        float v = 0.f;
        if (j <= i) { v = qp[i*(i+1)/2 + j]; if (j == i) v = expf(v); }
        sL[i*P+j] = v;
    }
    __syncthreads();
    for (int idx = tid; idx < LAT*LAT; idx += blockDim.x) {
        int i = idx >> 6, j = idx & 63;
        int m = i < j ? i : j;
        float acc = 0.f;
        for (int k = 0; k <= m; k++) acc += sL[i*P+k] * sL[j*P+k];
        g_Q[idx] = acc;
    }
}

__global__ void k_encoder(const float* __restrict__ x,
                          const float* __restrict__ W1, const float* __restrict__ b1,
                          const float* __restrict__ Wm, const float* __restrict__ bm,
                          const float* __restrict__ Wl, const float* __restrict__ bl) {
    __shared__ float xs[OBS];
    __shared__ float h[HID];
    int tok = blockIdx.x, tid = threadIdx.x;
    if (tid < OBS) xs[tid] = x[tok*OBS + tid];
    __syncthreads();
    for (int j = tid; j < HID; j += blockDim.x) {
        float acc = b1[j];
#pragma unroll
        for (int k = 0; k < OBS; k++) acc += xs[k] * W1[k*HID + j];
        h[j] = fmaxf(acc, 0.f);
    }
    __syncthreads();
    if (tid < LAT) {
        float acc = bm[tid];
        for (int j = 0; j < HID; j++) acc += h[j] * Wm[j*LAT + tid];
        g_zmu[tok*LAT + tid] = acc;
    } else if (tid < 2*LAT) {
        int o = tid - LAT;
        float acc = bl[o];
        for (int j = 0; j < HID; j++) acc += h[j] * Wl[j*LAT + o];
        g_sig[tok*LAT + o] = expf(0.5f * acc);
    }
}

__global__ void __launch_bounds__(256, 1)
k_filter(const float* __restrict__ Amat, const float* __restrict__ bvec_g,
         const int* __restrict__ mask, float* __restrict__ out_ll) {
    extern __shared__ float sm[];
    float* sA   = sm;
    float* sAT  = sA   + LAT*P;
    float* sQ   = sAT  + LAT*P;
    float* sSig = sQ   + LAT*P;
    float* sT1  = sSig + LAT*P;
    float* sSp  = sT1  + LAT*P;
    float* sS   = sSp  + LAT*P;
    float* sK   = sS   + LAT*P;
    float* sT   = sK   + LAT*P;
    float* sZ   = sT   + LAT*P;
    float* vb   = sZ   + LAT*P;
    float* mu    = vb;          float* mup  = mu    + 64;
    float* r     = mup  + 64;   float* rd   = r     + 64;
    float* bv    = rd   + 64;   float* dvec = bv    + 64;
    float* invd  = dvec + 64;   float* scal = invd  + 64;  // [0..2]
    float* psq   = scal + 8;    float* plg  = psq   + 4;
    float* sU    = plg  + 4;    // 512 floats

    int b = blockIdx.x, tid = threadIdx.x;

    for (int idx = tid; idx < LAT*LAT; idx += 256) {
        int i = idx >> 6, j = idx & 63;
        float a = Amat[idx];
        sA [i*P+j] = a;
        sAT[j*P+i] = a;
        sQ [i*P+j] = g_Q[idx];
        sSig[i*P+j] = (i == j) ? 1.f : 0.f;
    }
    if (tid < 64) { mu[tid] = 0.f; bv[tid] = bvec_g[tid]; }
    if (tid == 0) scal[2] = 0.f;
    __syncthreads();

    for (int t = 0; t < Tn; t++) {
        int base = (b*Tn + t) * LAT;
        int m = mask[b*Tn + t];

        if (tid < 64) {
            float acc = bv[tid];
            for (int k = 0; k < 64; k++) acc += sAT[k*P+tid] * mu[k];
            mup[tid] = acc;
            r[tid]   = g_zmu[base + tid] - acc;
            rd[tid]  = g_sig[base + tid];
        }
        __syncthreads();

        mm64<0,false,false>(sT1, sA, sSig, nullptr, nullptr);   // T1 = A Sig
        __syncthreads();
        mm64<1,false,false>(sSp, sT1, sAT, nullptr, sQ);        // Sp = T1 A^T + Q
        __syncthreads();

        if (m) {
            if (tid < 64) mu[tid] = mup[tid];
            for (int idx = tid; idx < 1024; idx += 256) {
                int row = idx >> 4, c4 = (idx & 15) * 4;
                *(float4*)&sSig[row*P + c4] = *(const float4*)&sSp[row*P + c4];
            }
        } else {
            for (int idx = tid; idx < 4096; idx += 256) {
                int i = idx >> 6, j = idx & 63;
                float v = sSp[i*P+j];
                if (i == j) v += rd[i];
                sS[i*P+j] = v;
            }
            chol64b(sS, dvec, invd);                 // L in sS (+ its final barrier)
            trinv64(sS, invd, sT, sU);               // T = L^-1 (+ its final barrier)

            mm64<0,false,false>(sZ, sT, sSp, nullptr, nullptr);  // Z = T Sp
            if (tid < 64) {                          // alpha = T r ; log pivots
                float a = 0.f;
                for (int k = 0; k < 64; k++) a += sT[tid*P+k] * r[k];
                float sq = a * a;
                float lg = logf(dvec[tid]);
#pragma unroll
                for (int o = 16; o; o >>= 1) {
                    sq += __shfl_xor_sync(0xffffffffu, sq, o);
                    lg += __shfl_xor_sync(0xffffffffu, lg, o);
                }
                if ((tid & 31) == 0) { psq[tid>>5] = sq; plg[tid>>5] = lg; }
            }
            __syncthreads();

            mm64<0,true,false>(sK, sZ, sT, nullptr, nullptr);    // K = Z^T T
            __syncthreads();

            if (tid < 64) {
                float acc = mup[tid];
                for (int k = 0; k < 64; k++) acc += sK[tid*P+k] * r[k];
                mu[tid] = acc;
            }
            if (tid == 64)
                scal[2] += -0.5f * 64.f * L2PI - (plg[0]+plg[1]) - 0.5f * (psq[0]+psq[1]);
            mm64<2,false,false>(sT1, sK, sSp, nullptr, sSp);     // M1 = Sp - K Sp
            __syncthreads();
            jos64f(sSig, sT1, sK, rd);                           // Joseph form
        }
        __syncthreads();

        if (tid < 64) g_mf[base + tid] = mu[tid];
        for (int idx = tid; idx < 1024; idx += 256) {
            int row = idx >> 4, c4 = (idx & 15) * 4;
            *(float4*)&g_Sf[(size_t)base*64 + row*64 + c4] =
                *(const float4*)&sSig[row*P + c4];
        }
        __syncthreads();
    }
    if (tid == 0) out_ll[b] = scal[2];
}

__global__ void __launch_bounds__(256, 1)
k_smoother(const float* __restrict__ Amat, const float* __restrict__ bvec_g,
           float* __restrict__ out) {
    extern __shared__ float sm[];
    float* sA   = sm;
    float* sAT  = sA   + LAT*P;
    float* sQ   = sAT  + LAT*P;
    float* sSf  = sQ   + LAT*P;
    float* sSs  = sSf  + LAT*P;
    float* sY   = sSs  + LAT*P;
    float* sSp  = sY   + LAT*P;
    float* sS   = sSp  + LAT*P;
    float* sT   = sS   + LAT*P;
    float* sZ   = sT   + LAT*P;   // also reused as D
    float* vb   = sZ   + LAT*P;
    float* mfv    = vb;          float* mus  = mfv    + 64;
    float* dm     = mus  + 64;   float* bv   = dm     + 64;
    float* dvec   = bv   + 64;   float* invd = dvec   + 64;
    float* sU     = invd + 64;   // 512 floats

    int b = blockIdx.x, tid = threadIdx.x;
    float* out_mq = out + MQ_OFF;
    float* out_sq = out + SQ_OFF;

    for (int idx = tid; idx < LAT*LAT; idx += 256) {
        int i = idx >> 6, j = idx & 63;
        float a = Amat[idx];
        sA [i*P+j] = a;
        sAT[j*P+i] = a;
        sQ [i*P+j] = g_Q[idx];
    }
    size_t baseT = ((size_t)b*Tn + (Tn-1)) * LAT;
    if (tid < 64) {
        mus[tid] = g_mf[baseT + tid];
        bv[tid]  = bvec_g[tid];
        out_mq[baseT + tid] = mus[tid];
    }
    for (int idx = tid; idx < 1024; idx += 256) {
        int row = idx >> 4, c4 = (idx & 15) * 4;
        float4 v = *(const float4*)&g_Sf[baseT*64 + row*64 + c4];
        *(float4*)&sSs[row*P + c4] = v;
        *(float4*)&out_sq[baseT*64 + row*64 + c4] = v;
    }
    __syncthreads();

    for (int t = Tn - 2; t >= 0; t--) {
        size_t base = ((size_t)b*Tn + t) * LAT;
        if (tid < 64) mfv[tid] = g_mf[base + tid];
        for (int idx = tid; idx < 1024; idx += 256) {
            int row = idx >> 4, c4 = (idx & 15) * 4;
            *(float4*)&sSf[row*P + c4] = *(const float4*)&g_Sf[base*64 + row*64 + c4];
        }
        __syncthreads();

        if (tid < 64) {
            float acc = bv[tid];
            for (int k = 0; k < 64; k++) acc += sAT[k*P+tid] * mfv[k];
            dm[tid] = mus[tid] - acc;
        }
        __syncthreads();

        mm64<0,false,false>(sY, sA, sSf, nullptr, nullptr);     // Y0 = A Sf
        __syncthreads();
        mm64<1,false,false>(sSp, sY, sAT, nullptr, sQ);         // Sp = Y0 A^T + Q
        __syncthreads();
        for (int idx = tid; idx < 1024; idx += 256) {
            int row = idx >> 4, c4 = (idx & 15) * 4;
            *(float4*)&sS[row*P + c4] = *(const float4*)&sSp[row*P + c4];
        }
        chol64b(sS, dvec, invd);
        trinv64(sS, invd, sT, sU);                              // T = L^-1

        mm64<0,false,false>(sZ, sT, sY, nullptr, nullptr);      // Z = T Y0
        __syncthreads();
        mm64<0,true,false>(sY, sT, sZ, nullptr, nullptr);       // Y = T^T Z = Sp^-1 A Sf = G^T
        __syncthreads();

        if (tid < 64) {
            float acc = mfv[tid];
            for (int k = 0; k < 64; k++) acc += sY[k*P+tid] * dm[k];
            mus[tid] = acc;
        }
        mm64<0,true,true>(sZ, sY, sSs, sSp, nullptr);           // D = Y^T (Ss - Sp)
        __syncthreads();
        mm64<1,false,false>(sSs, sZ, sY, nullptr, sSf);         // Ss = Sf + D Y
        __syncthreads();

        if (tid < 64) out_mq[base + tid] = mus[tid];
        for (int idx = tid; idx < 1024; idx += 256) {
            int row = idx >> 4, c4 = (idx & 15) * 4;
            *(float4*)&out_sq[base*64 + row*64 + c4] = *(const float4*)&sSs[row*P + c4];
        }
        __syncthreads();
    }
}

__global__ void __launch_bounds__(256, 1)
k_sample(const float* __restrict__ eps,
         const float* __restrict__ Wd, const float* __restrict__ bd,
         float* __restrict__ out) {
    __shared__ __align__(16) float sM[LAT*P];
    __shared__ float ev[64], zv[64], dvec[64], invd[64];
    int tok = blockIdx.x, tid = threadIdx.x;
    const float* sq = out + SQ_OFF + (size_t)tok * (LAT*LAT);
    const float* mq = out + MQ_OFF + tok * LAT;

    for (int idx = tid; idx < LAT*LAT; idx += 256) {
        int i = idx >> 6, j = idx & 63;
        sM[i*P+j] = sq[idx] + ((i == j) ? 1e-5f : 0.f);
    }
    if (tid < 64) ev[tid] = eps[tok*LAT + tid];
    chol64b(sM, dvec, invd);   // leading internal barrier covers the writes

    if (tid < 64) {
        float acc = mq[tid];
        for (int j = 0; j <= tid; j++) acc += sM[tid*P+j] * ev[j];
        zv[tid] = acc;
    }
    __syncthreads();
    if (tid < OBS) {
        float acc = bd[tid];
        for (int i = 0; i < 64; i++) acc += zv[i] * Wd[i*OBS + tid];
        out[XR_OFF + tok*OBS + tid] = acc;
    }
}

// ========================== launch ====================================

extern "C" void kernel_launch(void* const* d_in, const int* in_sizes, int n_in,
                              void* d_out, int out_size) {
    const float* x    = (const float*)d_in[0];
    const int*   mask = (const int*)  d_in[1];
    const float* eps  = (const float*)d_in[2];
    const float* W1   = (const float*)d_in[3];
    const float* b1   = (const float*)d_in[4];
    const float* Wm   = (const float*)d_in[5];
    const float* bm   = (const float*)d_in[6];
    const float* Wl   = (const float*)d_in[7];
    const float* bl   = (const float*)d_in[8];
    const float* Wd   = (const float*)d_in[9];
    const float* bd   = (const float*)d_in[10];
    const float* A    = (const float*)d_in[11];
    const float* bvec = (const float*)d_in[12];
    const float* Qp   = (const float*)d_in[13];
    float* out = (float*)d_out;

    k_buildQ <<<1, 256>>>(Qp);
    k_encoder<<<Bn*Tn, 128>>>(x, W1, b1, Wm, bm, Wl, bl);

    size_t smemF = (size_t)(10*LAT*P + 8*64 + 16 + 512) * sizeof(float);
    cudaFuncSetAttribute(k_filter, cudaFuncAttributeMaxDynamicSharedMemorySize, (int)smemF);
    k_filter<<<Bn, 256, smemF>>>(A, bvec, mask, out + LL_OFF);

    size_t smemS = (size_t)(10*LAT*P + 6*64 + 512) * sizeof(float);
    cudaFuncSetAttribute(k_smoother, cudaFuncAttributeMaxDynamicSharedMemorySize, (int)smemS);
    k_smoother<<<Bn, 256, smemS>>>(A, bvec, out);

    k_sample<<<Bn*Tn, 256>>>(eps, Wd, bd, out);
}